// round 1
// baseline (speedup 1.0000x reference)
#include <cuda_runtime.h>
#include <math.h>

// ---------------------------------------------------------------------------
// SSMXLSTMFusion: D=512, S=3, BATCH=256, H=8, HD=64
// Key trick: expm(delta*A) @ h_prev computed as batched Taylor series on the
// vector (24 sequential GEMMs of 256x512x512) instead of 256 matrix expms.
// ---------------------------------------------------------------------------

#define DD    512
#define BB    256
#define SS    3
#define KTAY  24

// ------------------------- scratch (device globals) ------------------------
__device__ float g_h1   [BB*DD];
__device__ float g_delta[BB];
__device__ float g_bx   [BB*DD];
__device__ float g_T0   [BB*DD];
__device__ float g_T1   [BB*DD];
__device__ float g_gates[SS*BB*4*DD];
__device__ float g_q    [BB*DD];
__device__ float g_k    [SS*BB*DD];
__device__ float g_v    [SS*BB*DD];
__device__ float g_ctx  [BB*DD];
__device__ float g_fused[BB*DD];
__device__ float g_comb [BB*5*DD];
__device__ float g_pre  [BB*DD];

// ------------------------- generic GEMM: C = X @ W^T -----------------------
// X: [M,K] row-major (row stride K), W: [N,K] row-major, C: [M,N].
// z-dim batches with strides sX/sW/sC/sB1/sB2 (elements).
// Epilogue: v = acc * smul * rowscale[m]?  (+ bias[n]) (+ bias2[n]);
//           C = v or C += v (addC); optional accum[m,n] += v.
template<int BM,int BN,int BK,int TM,int TN>
__global__ void __launch_bounds__((BM/TM)*(BN/TN))
gemm_tn(const float* __restrict__ X, long sX,
        const float* __restrict__ W, long sW,
        float* __restrict__ C, long sC,
        int M, int N, int K,
        const float* __restrict__ bias,  long sB1,
        const float* __restrict__ bias2, long sB2,
        const float* __restrict__ rowscale, float smul,
        float* __restrict__ accum, int addC)
{
    constexpr int THREADS = (BM/TM)*(BN/TN);
    __shared__ float As[BK][BM+1];
    __shared__ float Ws[BK][BN+1];

    const int z = blockIdx.z;
    X += (long)z * sX;
    W += (long)z * sW;
    C += (long)z * sC;
    const float* B1 = bias  ? bias  + (long)z * sB1 : nullptr;
    const float* B2 = bias2 ? bias2 + (long)z * sB2 : nullptr;

    const int tid = threadIdx.x;
    const int tx  = tid % (BN/TN);
    const int ty  = tid / (BN/TN);
    const int row0 = blockIdx.y * BM;
    const int col0 = blockIdx.x * BN;

    float acc[TM][TN] = {};

    for (int k0 = 0; k0 < K; k0 += BK) {
        #pragma unroll
        for (int e = tid; e < BM*BK; e += THREADS) {
            int m = e / BK, kk = e % BK;
            As[kk][m] = X[(long)(row0 + m) * K + k0 + kk];
        }
        #pragma unroll
        for (int e = tid; e < BN*BK; e += THREADS) {
            int n = e / BK, kk = e % BK;
            Ws[kk][n] = W[(long)(col0 + n) * K + k0 + kk];
        }
        __syncthreads();
        #pragma unroll
        for (int kk = 0; kk < BK; kk++) {
            float a[TM], b[TN];
            #pragma unroll
            for (int i = 0; i < TM; i++) a[i] = As[kk][ty*TM + i];
            #pragma unroll
            for (int j = 0; j < TN; j++) b[j] = Ws[kk][tx*TN + j];
            #pragma unroll
            for (int i = 0; i < TM; i++)
                #pragma unroll
                for (int j = 0; j < TN; j++)
                    acc[i][j] = fmaf(a[i], b[j], acc[i][j]);
        }
        __syncthreads();
    }

    #pragma unroll
    for (int i = 0; i < TM; i++) {
        int m = row0 + ty*TM + i;
        float rs = smul * (rowscale ? rowscale[m] : 1.0f);
        #pragma unroll
        for (int j = 0; j < TN; j++) {
            int n = col0 + tx*TN + j;
            float v = acc[i][j] * rs;
            if (B1) v += B1[n];
            if (B2) v += B2[n];
            long idx = (long)m * N + n;
            if (addC) C[idx] += v; else C[idx] = v;
            if (accum) accum[idx] += v;
        }
    }
}

// ------------------------- layernorm (+ optional exact GELU) ----------------
// One block per row of 512; 256 threads, 2 elements each.
__global__ void ln_act_kernel(const float* __restrict__ in,
                              const float* __restrict__ g,
                              const float* __restrict__ b,
                              float* __restrict__ out, int do_gelu)
{
    __shared__ float red[256];
    int row = blockIdx.x, t = threadIdx.x;
    const float* r = in + (long)row * DD;
    float x0 = r[t], x1 = r[t + 256];

    red[t] = x0 + x1; __syncthreads();
    for (int o = 128; o > 0; o >>= 1) { if (t < o) red[t] += red[t+o]; __syncthreads(); }
    float mean = red[0] * (1.0f/DD);
    __syncthreads();

    float d0 = x0 - mean, d1 = x1 - mean;
    red[t] = d0*d0 + d1*d1; __syncthreads();
    for (int o = 128; o > 0; o >>= 1) { if (t < o) red[t] += red[t+o]; __syncthreads(); }
    float inv = rsqrtf(red[0] * (1.0f/DD) + 1e-5f);

    float y0 = d0 * inv * g[t]     + b[t];
    float y1 = d1 * inv * g[t+256] + b[t+256];
    if (do_gelu) {
        y0 = 0.5f * y0 * (1.0f + erff(y0 * 0.70710678118654752f));
        y1 = 0.5f * y1 * (1.0f + erff(y1 * 0.70710678118654752f));
    }
    out[(long)row * DD + t]       = y0;
    out[(long)row * DD + t + 256] = y1;
}

// ------------------------- delta = softplus(h1 . w2 + b2) -------------------
__global__ void rowdot_softplus_kernel(const float* __restrict__ h1,
                                       const float* __restrict__ w2,
                                       const float* __restrict__ b2,
                                       float* __restrict__ delta)
{
    __shared__ float red[256];
    int row = blockIdx.x, t = threadIdx.x;
    const float* r = h1 + (long)row * DD;
    red[t] = r[t]*w2[t] + r[t+256]*w2[t+256];
    __syncthreads();
    for (int o = 128; o > 0; o >>= 1) { if (t < o) red[t] += red[t+o]; __syncthreads(); }
    if (t == 0) {
        float z = red[0] + b2[0];
        delta[row] = (z > 20.0f) ? z : log1pf(expf(z));
    }
}

// ------------------------- h_ssm += delta[b] * bx ---------------------------
__global__ void hssm_finalize_kernel(float* __restrict__ hssm,
                                     const float* __restrict__ delta,
                                     const float* __restrict__ bx)
{
    int i = blockIdx.x * blockDim.x + threadIdx.x;
    if (i < BB*DD) hssm[i] += delta[i >> 9] * bx[i];
}

// ------------------------- LSTM pointwise ----------------------------------
__device__ __forceinline__ float sigf(float x) { return 1.0f / (1.0f + expf(-x)); }

__global__ void lstm_point_kernel(const float* __restrict__ gates,
                                  const float* __restrict__ lstm_c,
                                  const float* __restrict__ decays,
                                  float* __restrict__ h_new,
                                  float* __restrict__ c_new)
{
    int idx = blockIdx.x * blockDim.x + threadIdx.x;
    if (idx >= SS*BB*DD) return;
    int s = idx / (BB*DD);
    int r = idx - s * (BB*DD);
    int b = r >> 9;
    int d = r & 511;
    const float* gp = gates + ((long)s * BB + b) * (4*DD);
    float i_g = sigf(gp[d]);
    float f_g = sigf(gp[DD + d]);
    float g_g = tanhf(gp[2*DD + d]);
    float o_g = sigf(gp[3*DD + d]);
    float c   = lstm_c[idx];
    float craw = f_g * c + i_g * g_g;
    float hn   = o_g * tanhf(craw);
    float dec  = decays[s];
    h_new[idx] = hn;
    c_new[idx] = dec * c + (1.0f - dec) * craw;
}

// ------------------------- attention (3 keys, warp per (b,h)) ---------------
__global__ void attn_kernel(const float* __restrict__ q,
                            const float* __restrict__ k,
                            const float* __restrict__ v,
                            float* __restrict__ ctx)
{
    int b    = blockIdx.x;
    int warp = threadIdx.x >> 5;   // head 0..7
    int lane = threadIdx.x & 31;

    const float* qp = q + (long)b * DD + warp * 64;
    float q0 = qp[lane], q1 = qp[lane + 32];

    float sc[SS];
    #pragma unroll
    for (int s = 0; s < SS; s++) {
        const float* kp = k + ((long)(s*BB + b) * DD) + warp * 64;
        float d = q0 * kp[lane] + q1 * kp[lane + 32];
        #pragma unroll
        for (int o = 16; o > 0; o >>= 1) d += __shfl_xor_sync(0xffffffff, d, o);
        sc[s] = d * 0.125f;   // 1/sqrt(64)
    }
    float m = fmaxf(sc[0], fmaxf(sc[1], sc[2]));
    float e[SS], sum = 0.0f;
    #pragma unroll
    for (int s = 0; s < SS; s++) { e[s] = expf(sc[s] - m); sum += e[s]; }
    float inv = 1.0f / sum;

    float c0 = 0.0f, c1 = 0.0f;
    #pragma unroll
    for (int s = 0; s < SS; s++) {
        const float* vp = v + ((long)(s*BB + b) * DD) + warp * 64;
        float w = e[s] * inv;
        c0 += w * vp[lane];
        c1 += w * vp[lane + 32];
    }
    ctx[(long)b * DD + warp*64 + lane]      = c0;
    ctx[(long)b * DD + warp*64 + lane + 32] = c1;
}

// ---------------------------------------------------------------------------
extern "C" void kernel_launch(void* const* d_in, const int* in_sizes, int n_in,
                              void* d_out, int out_size)
{
    (void)in_sizes; (void)n_in; (void)out_size;

    const float* x        = (const float*)d_in[0];
    const float* h_prev   = (const float*)d_in[1];
    const float* lstm_h   = (const float*)d_in[2];
    const float* lstm_c   = (const float*)d_in[3];
    const float* A        = (const float*)d_in[4];
    const float* Bm       = (const float*)d_in[5];
    const float* dn_w1    = (const float*)d_in[6];
    const float* dn_b1    = (const float*)d_in[7];
    const float* dn_g     = (const float*)d_in[8];
    const float* dn_beta  = (const float*)d_in[9];
    const float* dn_w2    = (const float*)d_in[10];
    const float* dn_b2    = (const float*)d_in[11];
    const float* lstm_wih = (const float*)d_in[12];
    const float* lstm_whh = (const float*)d_in[13];
    const float* lstm_bih = (const float*)d_in[14];
    const float* lstm_bhh = (const float*)d_in[15];
    const float* decays   = (const float*)d_in[16];
    const float* attn_in_w  = (const float*)d_in[17];
    const float* attn_in_b  = (const float*)d_in[18];
    const float* attn_out_w = (const float*)d_in[19];
    const float* attn_out_b = (const float*)d_in[20];
    const float* proj_w   = (const float*)d_in[21];
    const float* proj_b   = (const float*)d_in[22];
    const float* proj_g   = (const float*)d_in[23];
    const float* proj_beta= (const float*)d_in[24];

    float* out = (float*)d_out;
    // output tuple layout: (output, h_ssm, h_new, c_new)
    float* out_y    = out;                 // 256*512
    float* out_hssm = out + BB*DD;         // 256*512
    float* out_hnew = out + 2*BB*DD;       // 3*256*512
    float* out_cnew = out + 2*BB*DD + SS*BB*DD;

    float *p_h1, *p_delta, *p_bx, *p_T0, *p_T1, *p_gates,
          *p_q, *p_k, *p_v, *p_ctx, *p_fused, *p_comb, *p_pre;
    cudaGetSymbolAddress((void**)&p_h1,    g_h1);
    cudaGetSymbolAddress((void**)&p_delta, g_delta);
    cudaGetSymbolAddress((void**)&p_bx,    g_bx);
    cudaGetSymbolAddress((void**)&p_T0,    g_T0);
    cudaGetSymbolAddress((void**)&p_T1,    g_T1);
    cudaGetSymbolAddress((void**)&p_gates, g_gates);
    cudaGetSymbolAddress((void**)&p_q,     g_q);
    cudaGetSymbolAddress((void**)&p_k,     g_k);
    cudaGetSymbolAddress((void**)&p_v,     g_v);
    cudaGetSymbolAddress((void**)&p_ctx,   g_ctx);
    cudaGetSymbolAddress((void**)&p_fused, g_fused);
    cudaGetSymbolAddress((void**)&p_comb,  g_comb);
    cudaGetSymbolAddress((void**)&p_pre,   g_pre);

    // GEMM configs:
    //  cfgA: 64x64x16, 4x4 microtile (better FMA/smem ratio, for big grids)
    //  cfgB: 32x32x32, 2x2 microtile (128 blocks for 256x512 outputs)
    #define GEMM_A gemm_tn<64,64,16,4,4>
    #define GEMM_B gemm_tn<32,32,32,2,2>

    // ---- 1. h1 = gelu(layernorm(x @ dn_w1^T + dn_b1)) ----
    GEMM_B<<<dim3(DD/32, BB/32, 1), 256>>>(
        x, 0, dn_w1, 0, p_h1, 0, BB, DD, DD,
        dn_b1, 0, nullptr, 0, nullptr, 1.0f, nullptr, 0);
    ln_act_kernel<<<BB, 256>>>(p_h1, dn_g, dn_beta, p_h1, 1);

    // ---- 2. delta = softplus(h1 @ dn_w2^T + dn_b2) ----
    rowdot_softplus_kernel<<<BB, 256>>>(p_h1, dn_w2, dn_b2, p_delta);

    // ---- 3. bx = x @ Bm^T ----
    GEMM_B<<<dim3(DD/32, BB/32, 1), 256>>>(
        x, 0, Bm, 0, p_bx, 0, BB, DD, DD,
        nullptr, 0, nullptr, 0, nullptr, 1.0f, nullptr, 0);

    // ---- 4. Taylor series: h_ssm = expm(delta*A) @ h_prev ----
    cudaMemcpyAsync(out_hssm, h_prev, sizeof(float)*BB*DD,
                    cudaMemcpyDeviceToDevice, 0);
    cudaMemcpyAsync(p_T0, h_prev, sizeof(float)*BB*DD,
                    cudaMemcpyDeviceToDevice, 0);
    {
        float* Ta = p_T0; float* Tb = p_T1;
        for (int kk = 1; kk <= KTAY; kk++) {
            GEMM_B<<<dim3(DD/32, BB/32, 1), 256>>>(
                Ta, 0, A, 0, Tb, 0, BB, DD, DD,
                nullptr, 0, nullptr, 0,
                p_delta, 1.0f / (float)kk, out_hssm, 0);
            float* t = Ta; Ta = Tb; Tb = t;
        }
    }
    hssm_finalize_kernel<<<(BB*DD)/256, 256>>>(out_hssm, p_delta, p_bx);

    // ---- 5. LSTM gates: gates[s] = x @ wih[s]^T + h[s] @ whh[s]^T + biases ----
    GEMM_A<<<dim3(4*DD/64, BB/64, SS), 256>>>(
        x, 0, lstm_wih, (long)4*DD*DD, p_gates, (long)BB*4*DD,
        BB, 4*DD, DD,
        lstm_bih, 4*DD, lstm_bhh, 4*DD, nullptr, 1.0f, nullptr, 0);
    GEMM_A<<<dim3(4*DD/64, BB/64, SS), 256>>>(
        lstm_h, (long)BB*DD, lstm_whh, (long)4*DD*DD, p_gates, (long)BB*4*DD,
        BB, 4*DD, DD,
        nullptr, 0, nullptr, 0, nullptr, 1.0f, nullptr, 1);
    lstm_point_kernel<<<(SS*BB*DD)/256, 256>>>(
        p_gates, lstm_c, decays, out_hnew, out_cnew);

    // ---- 6. q/k/v ----
    GEMM_B<<<dim3(DD/32, BB/32, 1), 256>>>(
        out_hssm, 0, attn_in_w, 0, p_q, 0, BB, DD, DD,
        attn_in_b, 0, nullptr, 0, nullptr, 1.0f, nullptr, 0);
    GEMM_A<<<dim3(DD/64, (SS*BB)/64, 1), 256>>>(
        out_hnew, 0, attn_in_w + (long)DD*DD, 0, p_k, 0, SS*BB, DD, DD,
        attn_in_b + DD, 0, nullptr, 0, nullptr, 1.0f, nullptr, 0);
    GEMM_A<<<dim3(DD/64, (SS*BB)/64, 1), 256>>>(
        out_hnew, 0, attn_in_w + (long)2*DD*DD, 0, p_v, 0, SS*BB, DD, DD,
        attn_in_b + 2*DD, 0, nullptr, 0, nullptr, 1.0f, nullptr, 0);

    // ---- 7. attention + output proj ----
    attn_kernel<<<BB, 256>>>(p_q, p_k, p_v, p_ctx);
    GEMM_B<<<dim3(DD/32, BB/32, 1), 256>>>(
        p_ctx, 0, attn_out_w, 0, p_fused, 0, BB, DD, DD,
        attn_out_b, 0, nullptr, 0, nullptr, 1.0f, nullptr, 0);

    // ---- 8. combined = [h_ssm, fused, h_new0, h_new1, h_new2] ----
    {
        size_t dpitch = 5*DD*sizeof(float);
        size_t spitch = DD*sizeof(float);
        size_t w      = DD*sizeof(float);
        cudaMemcpy2DAsync(p_comb + 0,    dpitch, out_hssm, spitch, w, BB,
                          cudaMemcpyDeviceToDevice, 0);
        cudaMemcpy2DAsync(p_comb + DD,   dpitch, p_fused,  spitch, w, BB,
                          cudaMemcpyDeviceToDevice, 0);
        for (int s = 0; s < SS; s++) {
            cudaMemcpy2DAsync(p_comb + 2*DD + s*DD, dpitch,
                              out_hnew + (long)s*BB*DD, spitch, w, BB,
                              cudaMemcpyDeviceToDevice, 0);
        }
    }

    // ---- 9. output = layernorm(combined @ proj_w^T + proj_b) ----
    GEMM_B<<<dim3(DD/32, BB/32, 1), 256>>>(
        p_comb, 0, proj_w, 0, p_pre, 0, BB, DD, 5*DD,
        proj_b, 0, nullptr, 0, nullptr, 1.0f, nullptr, 0);
    ln_act_kernel<<<BB, 256>>>(p_pre, proj_g, proj_beta, out_y, 0);
}

// round 2
// speedup vs baseline: 1.4456x; 1.4456x over previous
#include <cuda_runtime.h>
#include <math.h>

// ---------------------------------------------------------------------------
// SSMXLSTMFusion: D=512, S=3, BATCH=256, H=8, HD=64
// Round 2: persistent Taylor-chain kernel (1 launch, grid barrier, split-K),
// merged GEMMs (h1|bx, k|v, dual-K LSTM), direct strided writes into comb,
// split-K proj. No memcpys.
// ---------------------------------------------------------------------------

#define DD    512
#define BB    256
#define SS    3
#define KT    18
#define TGRID 128

// ------------------------- scratch (device globals) ------------------------
__device__ float g_h1   [BB*DD];
__device__ float g_delta[BB];
__device__ float g_bx   [BB*DD];
__device__ float g_T    [BB*DD];
__device__ float g_part [4*BB*DD];
__device__ float g_gates[SS*BB*4*DD];
__device__ float g_q    [BB*DD];
__device__ float g_kv   [SS*BB*2*DD];
__device__ float g_ctx  [BB*DD];
__device__ float g_comb [BB*5*DD];
__device__ float g_pre  [BB*DD];

__device__ volatile unsigned g_bar_gen;
__device__ unsigned g_bar_cnt;

// ------------------------- grid barrier (persistent kernel) ----------------
__device__ __forceinline__ void grid_barrier()
{
    __syncthreads();
    if (threadIdx.x == 0) {
        unsigned mygen = g_bar_gen;
        __threadfence();
        unsigned t = atomicAdd(&g_bar_cnt, 1u);
        if (t == TGRID - 1) {
            g_bar_cnt = 0;
            __threadfence();
            g_bar_gen = mygen + 1;
        } else {
            while (g_bar_gen == mygen) { __nanosleep(32); }
            __threadfence();
        }
    }
    __syncthreads();
}

// ------------------------- persistent Taylor chain kernel ------------------
// h_ssm = expm(delta_b * A) @ h_prev_b + delta_b * (Bm @ x_b), via
// T_k = (delta/k) * (T_{k-1} @ A^T), y = sum_k T_k, for k=0..KT.
// 128 blocks: mt in [0,4) x nt in [0,8) x kz in [0,4) (split-K over 4x128).
__global__ void __launch_bounds__(256)
taylor_kernel(const float* __restrict__ h_prev,
              const float* __restrict__ A,
              const float* __restrict__ delta,
              const float* __restrict__ bx,
              float* __restrict__ T,
              float* __restrict__ part,
              float* __restrict__ y,
              float* __restrict__ comb)
{
    const int tid = threadIdx.x;
    const int bid = blockIdx.x;

    // element ownership for init / reduce / finalize (iteration-invariant)
    const int base = (bid * 256 + tid) * 4;     // covers 131072 = BB*DD
    const int row  = base >> 9;

    // init: T = h_prev; y (registers) = h_prev
    float4 yacc = *(const float4*)(h_prev + base);
    *(float4*)(T + base) = yacc;
    const float drow = delta[row];
    grid_barrier();

    const int mt = bid & 3;
    const int nt = (bid >> 2) & 7;
    const int kz = bid >> 5;
    const int j0 = kz * 128;
    const int tx = tid & 15, ty = tid >> 4;     // 16x16 threads, 4x4 micro
    const int ldm = tid >> 2;                   // gmem tile load row
    const int ldk = (tid & 3) * 4;              // gmem tile load k-offset

    __shared__ float As[16][68];
    __shared__ float Ws[16][68];

    float* mypart = part + (long)kz * (BB*DD);

    for (int k = 1; k <= KT; k++) {
        float acc[4][4] = {};
        // prefetch first sub-tile
        float4 av = *(const float4*)(T + (long)(mt*64 + ldm)*DD + j0 + ldk);
        float4 wv = *(const float4*)(A + (long)(nt*64 + ldm)*DD + j0 + ldk);
        for (int kb = 0; kb < 128; kb += 16) {
            __syncthreads();
            As[ldk+0][ldm] = av.x; As[ldk+1][ldm] = av.y;
            As[ldk+2][ldm] = av.z; As[ldk+3][ldm] = av.w;
            Ws[ldk+0][ldm] = wv.x; Ws[ldk+1][ldm] = wv.y;
            Ws[ldk+2][ldm] = wv.z; Ws[ldk+3][ldm] = wv.w;
            __syncthreads();
            if (kb + 16 < 128) {
                av = *(const float4*)(T + (long)(mt*64 + ldm)*DD + j0 + kb + 16 + ldk);
                wv = *(const float4*)(A + (long)(nt*64 + ldm)*DD + j0 + kb + 16 + ldk);
            }
            #pragma unroll
            for (int kk = 0; kk < 16; kk++) {
                float4 a = *(const float4*)&As[kk][ty*4];
                float4 b = *(const float4*)&Ws[kk][tx*4];
                acc[0][0] = fmaf(a.x, b.x, acc[0][0]);
                acc[0][1] = fmaf(a.x, b.y, acc[0][1]);
                acc[0][2] = fmaf(a.x, b.z, acc[0][2]);
                acc[0][3] = fmaf(a.x, b.w, acc[0][3]);
                acc[1][0] = fmaf(a.y, b.x, acc[1][0]);
                acc[1][1] = fmaf(a.y, b.y, acc[1][1]);
                acc[1][2] = fmaf(a.y, b.z, acc[1][2]);
                acc[1][3] = fmaf(a.y, b.w, acc[1][3]);
                acc[2][0] = fmaf(a.z, b.x, acc[2][0]);
                acc[2][1] = fmaf(a.z, b.y, acc[2][1]);
                acc[2][2] = fmaf(a.z, b.z, acc[2][2]);
                acc[2][3] = fmaf(a.z, b.w, acc[2][3]);
                acc[3][0] = fmaf(a.w, b.x, acc[3][0]);
                acc[3][1] = fmaf(a.w, b.y, acc[3][1]);
                acc[3][2] = fmaf(a.w, b.z, acc[3][2]);
                acc[3][3] = fmaf(a.w, b.w, acc[3][3]);
            }
        }
        // write 64x64 partial tile
        #pragma unroll
        for (int i = 0; i < 4; i++) {
            float4 v = make_float4(acc[i][0], acc[i][1], acc[i][2], acc[i][3]);
            *(float4*)(mypart + (long)(mt*64 + ty*4 + i)*DD + nt*64 + tx*4) = v;
        }
        grid_barrier();
        // deterministic fixed-order reduce over 4 partials + scale
        {
            float s = drow * (1.0f / (float)k);
            float4 p0 = *(const float4*)(part + base);
            float4 p1 = *(const float4*)(part + BB*DD + base);
            float4 p2 = *(const float4*)(part + 2*BB*DD + base);
            float4 p3 = *(const float4*)(part + 3*BB*DD + base);
            float4 t;
            t.x = (((p0.x + p1.x) + p2.x) + p3.x) * s;
            t.y = (((p0.y + p1.y) + p2.y) + p3.y) * s;
            t.z = (((p0.z + p1.z) + p2.z) + p3.z) * s;
            t.w = (((p0.w + p1.w) + p2.w) + p3.w) * s;
            *(float4*)(T + base) = t;
            yacc.x += t.x; yacc.y += t.y; yacc.z += t.z; yacc.w += t.w;
        }
        grid_barrier();
    }
    // finalize: y += delta * bx ; write out_hssm and comb[:, 0:512]
    {
        const int col = base & 511;
        float4 bxv = *(const float4*)(bx + base);
        yacc.x += drow * bxv.x;
        yacc.y += drow * bxv.y;
        yacc.z += drow * bxv.z;
        yacc.w += drow * bxv.w;
        *(float4*)(y + base) = yacc;
        *(float4*)(comb + (long)row*2560 + col) = yacc;
    }
}

// ------------------------- generic GEMM: C = X @ W^T (+ X2 @ W2^T) ---------
// N-split: columns n >= nsplit use weight rows Wn2, write Cn2, bias biasn2.
template<int BM,int BN,int BK,int TM,int TN>
__global__ void __launch_bounds__((BM/TM)*(BN/TN))
gemm_tn(const float* __restrict__ X,  long sX,  int ldX,
        const float* __restrict__ W,  long sW,  int ldW,
        const float* __restrict__ X2, long sX2, int ldX2,
        const float* __restrict__ W2, long sW2, int ldW2,
        float* __restrict__ C, long sC, int ldC,
        int M, int N, int K,
        const float* __restrict__ bias,  long sB1,
        const float* __restrict__ bias2, long sB2,
        const float* __restrict__ Wn2, float* __restrict__ Cn2,
        const float* __restrict__ biasn2, int nsplit)
{
    constexpr int THREADS = (BM/TM)*(BN/TN);
    __shared__ float As[BK][BM+1];
    __shared__ float Ws[BK][BN+1];

    const int z = blockIdx.z;
    const int tid = threadIdx.x;
    const int tx  = tid % (BN/TN);
    const int ty  = tid / (BN/TN);
    const int row0 = blockIdx.y * BM;
    const int col0 = blockIdx.x * BN;

    float acc[TM][TN] = {};

    const int npass = X2 ? 2 : 1;
    for (int pass = 0; pass < npass; pass++) {
        const float* Xp = pass ? X2 + (long)z*sX2 : X + (long)z*sX;
        const int ldXp  = pass ? ldX2 : ldX;
        const float* Wp = pass ? W2 + (long)z*sW2 : W + (long)z*sW;
        const int ldWp  = pass ? ldW2 : ldW;

        for (int k0 = 0; k0 < K; k0 += BK) {
            #pragma unroll
            for (int e = tid; e < BM*BK; e += THREADS) {
                int m = e / BK, kk = e % BK;
                As[kk][m] = Xp[(long)(row0 + m)*ldXp + k0 + kk];
            }
            #pragma unroll
            for (int e = tid; e < BN*BK; e += THREADS) {
                int n = e / BK, kk = e % BK;
                int ng = col0 + n;
                const float* wrow;
                if (pass == 0 && ng >= nsplit)
                    wrow = Wn2 + (long)(ng - nsplit)*ldWp;
                else
                    wrow = Wp + (long)ng*ldWp;
                Ws[kk][n] = wrow[k0 + kk];
            }
            __syncthreads();
            #pragma unroll
            for (int kk = 0; kk < BK; kk++) {
                float a[TM], b[TN];
                #pragma unroll
                for (int i = 0; i < TM; i++) a[i] = As[kk][ty*TM + i];
                #pragma unroll
                for (int j = 0; j < TN; j++) b[j] = Ws[kk][tx*TN + j];
                #pragma unroll
                for (int i = 0; i < TM; i++)
                    #pragma unroll
                    for (int j = 0; j < TN; j++)
                        acc[i][j] = fmaf(a[i], b[j], acc[i][j]);
            }
            __syncthreads();
        }
    }

    #pragma unroll
    for (int i = 0; i < TM; i++) {
        int m = row0 + ty*TM + i;
        #pragma unroll
        for (int j = 0; j < TN; j++) {
            int n = col0 + tx*TN + j;
            float v = acc[i][j];
            if (n < nsplit) {
                if (bias)  v += bias [(long)z*sB1 + n];
                if (bias2) v += bias2[(long)z*sB2 + n];
                C[(long)z*sC + (long)m*ldC + n] = v;
            } else {
                if (biasn2) v += biasn2[n - nsplit];
                Cn2[(long)m*ldC + (n - nsplit)] = v;
            }
        }
    }
}

// ------------------------- layernorm (+ optional exact GELU) ----------------
__global__ void ln_act_kernel(const float* __restrict__ in,
                              const float* __restrict__ g,
                              const float* __restrict__ b,
                              float* __restrict__ out, int do_gelu)
{
    __shared__ float red[256];
    int row = blockIdx.x, t = threadIdx.x;
    const float* r = in + (long)row * DD;
    float x0 = r[t], x1 = r[t + 256];

    red[t] = x0 + x1; __syncthreads();
    for (int o = 128; o > 0; o >>= 1) { if (t < o) red[t] += red[t+o]; __syncthreads(); }
    float mean = red[0] * (1.0f/DD);
    __syncthreads();

    float d0 = x0 - mean, d1 = x1 - mean;
    red[t] = d0*d0 + d1*d1; __syncthreads();
    for (int o = 128; o > 0; o >>= 1) { if (t < o) red[t] += red[t+o]; __syncthreads(); }
    float inv = rsqrtf(red[0] * (1.0f/DD) + 1e-5f);

    float y0 = d0 * inv * g[t]     + b[t];
    float y1 = d1 * inv * g[t+256] + b[t+256];
    if (do_gelu) {
        y0 = 0.5f * y0 * (1.0f + erff(y0 * 0.70710678118654752f));
        y1 = 0.5f * y1 * (1.0f + erff(y1 * 0.70710678118654752f));
    }
    out[(long)row * DD + t]       = y0;
    out[(long)row * DD + t + 256] = y1;
}

// ------------------------- delta = softplus(h1 . w2 + b2) -------------------
__global__ void rowdot_softplus_kernel(const float* __restrict__ h1,
                                       const float* __restrict__ w2,
                                       const float* __restrict__ b2,
                                       float* __restrict__ delta)
{
    __shared__ float red[256];
    int row = blockIdx.x, t = threadIdx.x;
    const float* r = h1 + (long)row * DD;
    red[t] = r[t]*w2[t] + r[t+256]*w2[t+256];
    __syncthreads();
    for (int o = 128; o > 0; o >>= 1) { if (t < o) red[t] += red[t+o]; __syncthreads(); }
    if (t == 0) {
        float z = red[0] + b2[0];
        delta[row] = (z > 20.0f) ? z : log1pf(expf(z));
    }
}

// ------------------------- LSTM pointwise (also fills comb) ----------------
__device__ __forceinline__ float sigf(float x) { return 1.0f / (1.0f + expf(-x)); }

__global__ void lstm_point_kernel(const float* __restrict__ gates,
                                  const float* __restrict__ lstm_c,
                                  const float* __restrict__ decays,
                                  float* __restrict__ h_new,
                                  float* __restrict__ c_new,
                                  float* __restrict__ comb)
{
    int idx = blockIdx.x * blockDim.x + threadIdx.x;
    if (idx >= SS*BB*DD) return;
    int s = idx / (BB*DD);
    int r = idx - s * (BB*DD);
    int b = r >> 9;
    int d = r & 511;
    const float* gp = gates + ((long)s * BB + b) * (4*DD);
    float i_g = sigf(gp[d]);
    float f_g = sigf(gp[DD + d]);
    float g_g = tanhf(gp[2*DD + d]);
    float o_g = sigf(gp[3*DD + d]);
    float c   = lstm_c[idx];
    float craw = f_g * c + i_g * g_g;
    float hn   = o_g * tanhf(craw);
    float dec  = decays[s];
    h_new[idx] = hn;
    c_new[idx] = dec * c + (1.0f - dec) * craw;
    comb[(long)b * 2560 + 1024 + s*512 + d] = hn;
}

// ------------------------- attention (3 keys, warp per (b,h)) ---------------
// kv: [S*BB, 1024] with k in cols [0,512), v in cols [512,1024)
__global__ void attn_kernel(const float* __restrict__ q,
                            const float* __restrict__ kv,
                            float* __restrict__ ctx)
{
    int b    = blockIdx.x;
    int warp = threadIdx.x >> 5;   // head 0..7
    int lane = threadIdx.x & 31;

    const float* qp = q + (long)b * DD + warp * 64;
    float q0 = qp[lane], q1 = qp[lane + 32];

    float sc[SS];
    #pragma unroll
    for (int s = 0; s < SS; s++) {
        const float* kp = kv + (long)(s*BB + b) * 1024 + warp * 64;
        float d = q0 * kp[lane] + q1 * kp[lane + 32];
        #pragma unroll
        for (int o = 16; o > 0; o >>= 1) d += __shfl_xor_sync(0xffffffff, d, o);
        sc[s] = d * 0.125f;   // 1/sqrt(64)
    }
    float m = fmaxf(sc[0], fmaxf(sc[1], sc[2]));
    float e[SS], sum = 0.0f;
    #pragma unroll
    for (int s = 0; s < SS; s++) { e[s] = expf(sc[s] - m); sum += e[s]; }
    float inv = 1.0f / sum;

    float c0 = 0.0f, c1 = 0.0f;
    #pragma unroll
    for (int s = 0; s < SS; s++) {
        const float* vp = kv + (long)(s*BB + b) * 1024 + 512 + warp * 64;
        float w = e[s] * inv;
        c0 += w * vp[lane];
        c1 += w * vp[lane + 32];
    }
    ctx[(long)b * DD + warp*64 + lane]      = c0;
    ctx[(long)b * DD + warp*64 + lane + 32] = c1;
}

// ------------------------- proj split-K reduce ------------------------------
__global__ void proj_reduce_kernel(const float* __restrict__ part,
                                   const float* __restrict__ bias,
                                   float* __restrict__ out)
{
    int idx = blockIdx.x * blockDim.x + threadIdx.x;
    if (idx >= BB*DD) return;
    int n = idx & 511;
    float v = ((part[idx] + part[BB*DD + idx]) + part[2*BB*DD + idx])
              + part[3*BB*DD + idx] + bias[n];
    out[idx] = v;
}

// ---------------------------------------------------------------------------
extern "C" void kernel_launch(void* const* d_in, const int* in_sizes, int n_in,
                              void* d_out, int out_size)
{
    (void)in_sizes; (void)n_in; (void)out_size;

    const float* x        = (const float*)d_in[0];
    const float* h_prev   = (const float*)d_in[1];
    const float* lstm_h   = (const float*)d_in[2];
    const float* lstm_c   = (const float*)d_in[3];
    const float* A        = (const float*)d_in[4];
    const float* Bm       = (const float*)d_in[5];
    const float* dn_w1    = (const float*)d_in[6];
    const float* dn_b1    = (const float*)d_in[7];
    const float* dn_g     = (const float*)d_in[8];
    const float* dn_beta  = (const float*)d_in[9];
    const float* dn_w2    = (const float*)d_in[10];
    const float* dn_b2    = (const float*)d_in[11];
    const float* lstm_wih = (const float*)d_in[12];
    const float* lstm_whh = (const float*)d_in[13];
    const float* lstm_bih = (const float*)d_in[14];
    const float* lstm_bhh = (const float*)d_in[15];
    const float* decays   = (const float*)d_in[16];
    const float* attn_in_w  = (const float*)d_in[17];
    const float* attn_in_b  = (const float*)d_in[18];
    const float* attn_out_w = (const float*)d_in[19];
    const float* attn_out_b = (const float*)d_in[20];
    const float* proj_w   = (const float*)d_in[21];
    const float* proj_b   = (const float*)d_in[22];
    const float* proj_g   = (const float*)d_in[23];
    const float* proj_beta= (const float*)d_in[24];

    float* out = (float*)d_out;
    float* out_y    = out;                         // 256*512
    float* out_hssm = out + BB*DD;                 // 256*512
    float* out_hnew = out + 2*BB*DD;               // 3*256*512
    float* out_cnew = out + 2*BB*DD + SS*BB*DD;    // 3*256*512

    float *p_h1, *p_delta, *p_bx, *p_T, *p_part, *p_gates,
          *p_q, *p_kv, *p_ctx, *p_comb, *p_pre;
    cudaGetSymbolAddress((void**)&p_h1,    g_h1);
    cudaGetSymbolAddress((void**)&p_delta, g_delta);
    cudaGetSymbolAddress((void**)&p_bx,    g_bx);
    cudaGetSymbolAddress((void**)&p_T,     g_T);
    cudaGetSymbolAddress((void**)&p_part,  g_part);
    cudaGetSymbolAddress((void**)&p_gates, g_gates);
    cudaGetSymbolAddress((void**)&p_q,     g_q);
    cudaGetSymbolAddress((void**)&p_kv,    g_kv);
    cudaGetSymbolAddress((void**)&p_ctx,   g_ctx);
    cudaGetSymbolAddress((void**)&p_comb,  g_comb);
    cudaGetSymbolAddress((void**)&p_pre,   g_pre);

    #define GEMM_A gemm_tn<64,64,16,4,4>
    #define GEMM_B gemm_tn<32,32,32,2,2>

    // ---- 1. [h1 | bx] = x @ [dn_w1 | Bm]^T  (N-split GEMM, N=1024) ----
    GEMM_A<<<dim3(16, 4, 1), 256>>>(
        x, 0, DD,  dn_w1, 0, DD,
        nullptr, 0, 0,  nullptr, 0, 0,
        p_h1, 0, DD,  BB, 2*DD, DD,
        dn_b1, 0,  nullptr, 0,
        Bm, p_bx, nullptr, DD);
    ln_act_kernel<<<BB, 256>>>(p_h1, dn_g, dn_beta, p_h1, 1);

    // ---- 2. delta = softplus(h1 @ dn_w2^T + dn_b2) ----
    rowdot_softplus_kernel<<<BB, 256>>>(p_h1, dn_w2, dn_b2, p_delta);

    // ---- 3. persistent Taylor chain -> out_hssm + comb[:,0:512] ----
    taylor_kernel<<<TGRID, 256>>>(h_prev, A, p_delta, p_bx,
                                  p_T, p_part, out_hssm, p_comb);

    // ---- 4. LSTM gates (dual-K GEMM): x@wih^T + h@whh^T + biases ----
    GEMM_A<<<dim3(32, 4, SS), 256>>>(
        x, 0, DD,  lstm_wih, (long)4*DD*DD, DD,
        lstm_h, (long)BB*DD, DD,  lstm_whh, (long)4*DD*DD, DD,
        p_gates, (long)BB*4*DD, 4*DD,  BB, 4*DD, DD,
        lstm_bih, 4*DD,  lstm_bhh, 4*DD,
        nullptr, nullptr, nullptr, 4*DD);
    lstm_point_kernel<<<(SS*BB*DD)/256, 256>>>(
        p_gates, lstm_c, decays, out_hnew, out_cnew, p_comb);

    // ---- 5. [k|v] = h_new @ [Wk|Wv]^T  (contiguous rows of attn_in_w) ----
    GEMM_A<<<dim3(16, 12, 1), 256>>>(
        out_hnew, 0, DD,  attn_in_w + (long)DD*DD, 0, DD,
        nullptr, 0, 0,  nullptr, 0, 0,
        p_kv, 0, 2*DD,  SS*BB, 2*DD, DD,
        attn_in_b + DD, 0,  nullptr, 0,
        nullptr, nullptr, nullptr, 2*DD);

    // ---- 6. q = h_ssm @ Wq^T ----
    GEMM_B<<<dim3(16, 8, 1), 256>>>(
        out_hssm, 0, DD,  attn_in_w, 0, DD,
        nullptr, 0, 0,  nullptr, 0, 0,
        p_q, 0, DD,  BB, DD, DD,
        attn_in_b, 0,  nullptr, 0,
        nullptr, nullptr, nullptr, DD);

    // ---- 7. attention ----
    attn_kernel<<<BB, 256>>>(p_q, p_kv, p_ctx);

    // ---- 8. fused = ctx @ attn_out_w^T + b  ->  comb[:,512:1024] ----
    GEMM_B<<<dim3(16, 8, 1), 256>>>(
        p_ctx, 0, DD,  attn_out_w, 0, DD,
        nullptr, 0, 0,  nullptr, 0, 0,
        p_comb + DD, 0, 5*DD,  BB, DD, DD,
        attn_out_b, 0,  nullptr, 0,
        nullptr, nullptr, nullptr, DD);

    // ---- 9. proj (K=2560) split-K=4 -> partials -> reduce -> LN ----
    GEMM_A<<<dim3(8, 4, 4), 256>>>(
        p_comb, 640, 5*DD,  proj_w, 640, 5*DD,
        nullptr, 0, 0,  nullptr, 0, 0,
        p_part, (long)BB*DD, DD,  BB, DD, 640,
        nullptr, 0,  nullptr, 0,
        nullptr, nullptr, nullptr, DD);
    proj_reduce_kernel<<<(BB*DD + 255)/256, 256>>>(p_part, proj_b, p_pre);
    ln_act_kernel<<<BB, 256>>>(p_pre, proj_g, proj_beta, out_y, 0);
}

// round 4
// speedup vs baseline: 1.4840x; 1.0265x over previous
#include <cuda_runtime.h>
#include <cuda_bf16.h>
#include <math.h>
#include <cstdint>

// ---------------------------------------------------------------------------
// SSMXLSTMFusion: D=512, S=3, BATCH=256, H=8, HD=64
// Round 4: all GEMMs via mma.sync bf16 (hi/lo split emulating fp32, fp32
// accumulators). tcgen05 unavailable (PTX target sm_103, not sm_103a).
// Taylor chain with precomputed A^2..A^4 (4 terms per GEMM), KT=20.
// ---------------------------------------------------------------------------

#define DD    512
#define BB    256
#define SS    3

// ------------------------- scratch (device globals) ------------------------
__device__ float g_h1   [BB*DD];
__device__ float g_delta[BB];
__device__ float g_bx   [BB*DD];
__device__ float g_T    [BB*DD];
__device__ float g_U    [BB*4*DD];
__device__ float g_AT   [DD*DD];
__device__ float g_Wpow [4*DD*DD];
__device__ float g_part [4*BB*DD];
__device__ float g_gates[SS*BB*4*DD];
__device__ float g_q    [BB*DD];
__device__ float g_kv   [SS*BB*2*DD];
__device__ float g_ctx  [BB*DD];
__device__ float g_comb [BB*5*DD];
__device__ float g_pre  [BB*DD];

// ========================= mma.sync GEMM ====================================
// C[M,N] = X[M,K] @ W[N,K]^T in emulated fp32 (bf16 hi/lo, 3 cross products).
// Block tile: 128(M) x 128(N), 256 threads (warps 4m x 2n, warp tile 32x64).
// K staged in chunks of 64 fp32. z batches via sX/sW/sC. Optional dual-K
// second pass (X2,W2). N-split: cols >= nsplit use Wn2 rows -> Cn2/biasn2.

#define RSB   144              // smem row stride in bytes (72 bf16)
#define PLANE (128*RSB)        // 18432 B per plane
#define OFF_AHI 0
#define OFF_ALO (PLANE)
#define OFF_BHI (2*PLANE)
#define OFF_BLO (3*PLANE)
#define SM_TOTAL (4*PLANE)     // 73728 B

__device__ __forceinline__ uint32_t pack_bf16(float x0, float x1) {
    __nv_bfloat16 h0 = __float2bfloat16_rn(x0);
    __nv_bfloat16 h1 = __float2bfloat16_rn(x1);
    uint16_t u0 = *(uint16_t*)&h0, u1 = *(uint16_t*)&h1;
    return (uint32_t)u0 | ((uint32_t)u1 << 16);
}

// split 16 floats into hi/lo bf16 planes and store (row r, col c0..c0+15)
__device__ __forceinline__ void store_split(char* smem, int off_hi, int off_lo,
                                            int r, int c0, const float* f)
{
    uint32_t hi[8], lo[8];
    #pragma unroll
    for (int i = 0; i < 8; i++) {
        float x0 = f[2*i], x1 = f[2*i+1];
        __nv_bfloat16 h0 = __float2bfloat16_rn(x0);
        __nv_bfloat16 h1 = __float2bfloat16_rn(x1);
        float r0 = x0 - __bfloat162float(h0);
        float r1 = x1 - __bfloat162float(h1);
        uint16_t u0 = *(uint16_t*)&h0, u1 = *(uint16_t*)&h1;
        hi[i] = (uint32_t)u0 | ((uint32_t)u1 << 16);
        lo[i] = pack_bf16(r0, r1);
    }
    int base = r * RSB + c0 * 2;
    *(uint4*)(smem + off_hi + base)      = make_uint4(hi[0], hi[1], hi[2], hi[3]);
    *(uint4*)(smem + off_hi + base + 16) = make_uint4(hi[4], hi[5], hi[6], hi[7]);
    *(uint4*)(smem + off_lo + base)      = make_uint4(lo[0], lo[1], lo[2], lo[3]);
    *(uint4*)(smem + off_lo + base + 16) = make_uint4(lo[4], lo[5], lo[6], lo[7]);
}

__device__ __forceinline__ void mma_bf16(float* c, const uint32_t* a, const uint32_t* b)
{
    asm volatile(
        "mma.sync.aligned.m16n8k16.row.col.f32.bf16.bf16.f32 "
        "{%0,%1,%2,%3}, {%4,%5,%6,%7}, {%8,%9}, {%0,%1,%2,%3};"
        : "+f"(c[0]), "+f"(c[1]), "+f"(c[2]), "+f"(c[3])
        : "r"(a[0]), "r"(a[1]), "r"(a[2]), "r"(a[3]), "r"(b[0]), "r"(b[1]));
}

__global__ void __launch_bounds__(256)
gemm_tc(const float* __restrict__ X,  long sX,  int ldX,
        const float* __restrict__ W,  long sW,  int ldW,
        const float* __restrict__ X2, long sX2, int ldX2,
        const float* __restrict__ W2, long sW2, int ldW2,
        float* __restrict__ C, long sC, int ldC,
        int K,
        const float* __restrict__ bias,  long sB1,
        const float* __restrict__ bias2, long sB2,
        const float* __restrict__ Wn2,
        float* __restrict__ Cn2, int ldCn2,
        const float* __restrict__ biasn2,
        int nsplit)
{
    extern __shared__ char smem[];
    const int tid = threadIdx.x;
    const int lid = tid & 31;
    const int wid = tid >> 5;
    const int wm  = wid & 3;          // 0..3
    const int wn  = wid >> 2;         // 0..1
    const int gid = lid >> 2;         // 0..7
    const int tig = lid & 3;          // 0..3
    const int z  = blockIdx.z;
    const int m0 = blockIdx.y * 128;
    const int n0 = blockIdx.x * 128;
    const int m_base = wm * 32;
    const int n_base = wn * 64;

    float acc[2][8][4];
    #pragma unroll
    for (int i = 0; i < 2; i++)
        #pragma unroll
        for (int j = 0; j < 8; j++)
            #pragma unroll
            for (int k = 0; k < 4; k++) acc[i][j][k] = 0.0f;

    // loader thread mapping: row = pass*64 + tid>>2, cols (tid&3)*16..+15
    const int lrow = tid >> 2;
    const int lcol = (tid & 3) * 16;

    const int npass = X2 ? 2 : 1;
    for (int pass = 0; pass < npass; pass++) {
        const float* Xp = (pass ? X2 + (long)z*sX2 : X + (long)z*sX);
        const int ldXp  = pass ? ldX2 : ldX;
        Xp += (long)m0 * ldXp;
        const float* Wp = pass ? W2 + (long)z*sW2 : W + (long)z*sW;
        const int ldWp  = pass ? ldW2 : ldW;
        const float* Wn2p = pass ? nullptr : Wn2;

        for (int k0 = 0; k0 < K; k0 += 64) {
            __syncthreads();
            // ---- load + split A (128 x 64) ----
            #pragma unroll
            for (int p = 0; p < 2; p++) {
                int r = p*64 + lrow;
                const float* src = Xp + (long)r*ldXp + k0 + lcol;
                float f[16];
                *(float4*)(f+0)  = *(const float4*)(src+0);
                *(float4*)(f+4)  = *(const float4*)(src+4);
                *(float4*)(f+8)  = *(const float4*)(src+8);
                *(float4*)(f+12) = *(const float4*)(src+12);
                store_split(smem, OFF_AHI, OFF_ALO, r, lcol, f);
            }
            // ---- load + split B (128 x 64), nsplit row select ----
            #pragma unroll
            for (int p = 0; p < 2; p++) {
                int n = p*64 + lrow;
                int ng = n0 + n;
                const float* row = (Wn2p && ng >= nsplit)
                                 ? Wn2p + (long)(ng - nsplit)*ldWp
                                 : Wp   + (long)ng*ldWp;
                const float* src = row + k0 + lcol;
                float f[16];
                *(float4*)(f+0)  = *(const float4*)(src+0);
                *(float4*)(f+4)  = *(const float4*)(src+4);
                *(float4*)(f+8)  = *(const float4*)(src+8);
                *(float4*)(f+12) = *(const float4*)(src+12);
                store_split(smem, OFF_BHI, OFF_BLO, n, lcol, f);
            }
            __syncthreads();

            // ---- 4 k-steps of 16 ----
            #pragma unroll
            for (int ks = 0; ks < 4; ks++) {
                const int kb = (ks*16 + tig*2) * 2;   // byte offset of k pair
                uint32_t ahi[2][4], alo[2][4];
                #pragma unroll
                for (int mt = 0; mt < 2; mt++) {
                    int rb = (m_base + mt*16 + gid) * RSB;
                    ahi[mt][0] = *(const uint32_t*)(smem + OFF_AHI + rb + kb);
                    ahi[mt][1] = *(const uint32_t*)(smem + OFF_AHI + rb + 8*RSB + kb);
                    ahi[mt][2] = *(const uint32_t*)(smem + OFF_AHI + rb + kb + 16);
                    ahi[mt][3] = *(const uint32_t*)(smem + OFF_AHI + rb + 8*RSB + kb + 16);
                    alo[mt][0] = *(const uint32_t*)(smem + OFF_ALO + rb + kb);
                    alo[mt][1] = *(const uint32_t*)(smem + OFF_ALO + rb + 8*RSB + kb);
                    alo[mt][2] = *(const uint32_t*)(smem + OFF_ALO + rb + kb + 16);
                    alo[mt][3] = *(const uint32_t*)(smem + OFF_ALO + rb + 8*RSB + kb + 16);
                }
                uint32_t bhi[8][2], blo[8][2];
                #pragma unroll
                for (int nt = 0; nt < 8; nt++) {
                    int rb = (n_base + nt*8 + gid) * RSB;
                    bhi[nt][0] = *(const uint32_t*)(smem + OFF_BHI + rb + kb);
                    bhi[nt][1] = *(const uint32_t*)(smem + OFF_BHI + rb + kb + 16);
                    blo[nt][0] = *(const uint32_t*)(smem + OFF_BLO + rb + kb);
                    blo[nt][1] = *(const uint32_t*)(smem + OFF_BLO + rb + kb + 16);
                }
                #pragma unroll
                for (int mt = 0; mt < 2; mt++)
                    #pragma unroll
                    for (int nt = 0; nt < 8; nt++) {
                        mma_bf16(acc[mt][nt], ahi[mt], bhi[nt]);
                        mma_bf16(acc[mt][nt], ahi[mt], blo[nt]);
                        mma_bf16(acc[mt][nt], alo[mt], bhi[nt]);
                    }
            }
        }
    }

    // ---- epilogue ----
    #pragma unroll
    for (int mt = 0; mt < 2; mt++) {
        #pragma unroll
        for (int nt = 0; nt < 8; nt++) {
            int m = m0 + m_base + mt*16 + gid;
            int n = n0 + n_base + nt*8 + tig*2;
            #pragma unroll
            for (int half = 0; half < 2; half++) {
                int mm = m + half*8;
                #pragma unroll
                for (int cc = 0; cc < 2; cc++) {
                    int ng = n + cc;
                    float v = acc[mt][nt][half*2 + cc];
                    if (Cn2 && ng >= nsplit) {
                        if (biasn2) v += biasn2[ng - nsplit];
                        Cn2[(long)mm*ldCn2 + (ng - nsplit)] = v;
                    } else {
                        if (bias)  v += bias [(long)z*sB1 + ng];
                        if (bias2) v += bias2[(long)z*sB2 + ng];
                        C[(long)z*sC + (long)mm*ldC + ng] = v;
                    }
                }
            }
        }
    }
}

// ========================= small SIMT kernels ===============================
__global__ void transpose_copy_kernel(const float* __restrict__ A,
                                      float* __restrict__ AT,
                                      float* __restrict__ W0)
{
    __shared__ float t[32][33];
    int bx = blockIdx.x*32, by = blockIdx.y*32;
    int x = bx + threadIdx.x;
    #pragma unroll
    for (int i = 0; i < 32; i += 8) {
        int y = by + threadIdx.y + i;
        float v = A[(long)y*DD + x];
        t[threadIdx.y + i][threadIdx.x] = v;
        W0[(long)y*DD + x] = v;
    }
    __syncthreads();
    int xo = by + threadIdx.x;
    #pragma unroll
    for (int i = 0; i < 32; i += 8) {
        int yo = bx + threadIdx.y + i;
        AT[(long)yo*DD + xo] = t[threadIdx.x][threadIdx.y + i];
    }
}

__global__ void ln_act_kernel(const float* __restrict__ in,
                              const float* __restrict__ g,
                              const float* __restrict__ b,
                              float* __restrict__ out, int do_gelu)
{
    __shared__ float red[256];
    int row = blockIdx.x, t = threadIdx.x;
    const float* r = in + (long)row * DD;
    float x0 = r[t], x1 = r[t + 256];

    red[t] = x0 + x1; __syncthreads();
    for (int o = 128; o > 0; o >>= 1) { if (t < o) red[t] += red[t+o]; __syncthreads(); }
    float mean = red[0] * (1.0f/DD);
    __syncthreads();

    float d0 = x0 - mean, d1 = x1 - mean;
    red[t] = d0*d0 + d1*d1; __syncthreads();
    for (int o = 128; o > 0; o >>= 1) { if (t < o) red[t] += red[t+o]; __syncthreads(); }
    float inv = rsqrtf(red[0] * (1.0f/DD) + 1e-5f);

    float y0 = d0 * inv * g[t]     + b[t];
    float y1 = d1 * inv * g[t+256] + b[t+256];
    if (do_gelu) {
        y0 = 0.5f * y0 * (1.0f + erff(y0 * 0.70710678118654752f));
        y1 = 0.5f * y1 * (1.0f + erff(y1 * 0.70710678118654752f));
    }
    out[(long)row * DD + t]       = y0;
    out[(long)row * DD + t + 256] = y1;
}

__global__ void rowdot_softplus_kernel(const float* __restrict__ h1,
                                       const float* __restrict__ w2,
                                       const float* __restrict__ b2,
                                       float* __restrict__ delta)
{
    __shared__ float red[256];
    int row = blockIdx.x, t = threadIdx.x;
    const float* r = h1 + (long)row * DD;
    red[t] = r[t]*w2[t] + r[t+256]*w2[t+256];
    __syncthreads();
    for (int o = 128; o > 0; o >>= 1) { if (t < o) red[t] += red[t+o]; __syncthreads(); }
    if (t == 0) {
        float z = red[0] + b2[0];
        delta[row] = (z > 20.0f) ? z : log1pf(expf(z));
    }
}

// chain epilogue: U[b, j*512+n] = (A^{j+1} t_{k0})[n], j=0..3
__global__ void chain_epilogue_kernel(const float* __restrict__ U,
                                      const float* __restrict__ delta,
                                      float* __restrict__ T,
                                      float* __restrict__ y,
                                      int k0,
                                      const float* __restrict__ bx,
                                      float* __restrict__ comb,
                                      int last)
{
    int idx = blockIdx.x * blockDim.x + threadIdx.x;
    if (idx >= BB*DD) return;
    int b = idx >> 9, n = idx & 511;
    float d  = delta[b];
    float c1 = d / (float)(k0+1);
    float c2 = c1 * d / (float)(k0+2);
    float c3 = c2 * d / (float)(k0+3);
    float c4 = c3 * d / (float)(k0+4);
    const float* ub = U + (long)b * 2048;
    float t4 = c4 * ub[1536 + n];
    float yy = y[idx] + c1*ub[n] + c2*ub[512+n] + c3*ub[1024+n] + t4;
    if (last) {
        yy += d * bx[idx];
        comb[(long)b*2560 + n] = yy;
    }
    y[idx] = yy;
    T[idx] = t4;
}

__device__ __forceinline__ float sigf(float x) { return 1.0f / (1.0f + expf(-x)); }

__global__ void lstm_point_kernel(const float* __restrict__ gates,
                                  const float* __restrict__ lstm_c,
                                  const float* __restrict__ decays,
                                  float* __restrict__ h_new,
                                  float* __restrict__ c_new,
                                  float* __restrict__ comb)
{
    int idx = blockIdx.x * blockDim.x + threadIdx.x;
    if (idx >= SS*BB*DD) return;
    int s = idx / (BB*DD);
    int r = idx - s * (BB*DD);
    int b = r >> 9;
    int d = r & 511;
    const float* gp = gates + ((long)s * BB + b) * (4*DD);
    float i_g = sigf(gp[d]);
    float f_g = sigf(gp[DD + d]);
    float g_g = tanhf(gp[2*DD + d]);
    float o_g = sigf(gp[3*DD + d]);
    float c   = lstm_c[idx];
    float craw = f_g * c + i_g * g_g;
    float hn   = o_g * tanhf(craw);
    float dec  = decays[s];
    h_new[idx] = hn;
    c_new[idx] = dec * c + (1.0f - dec) * craw;
    comb[(long)b * 2560 + 1024 + s*512 + d] = hn;
}

__global__ void attn_kernel(const float* __restrict__ q,
                            const float* __restrict__ kv,
                            float* __restrict__ ctx)
{
    int b    = blockIdx.x;
    int warp = threadIdx.x >> 5;
    int lane = threadIdx.x & 31;

    const float* qp = q + (long)b * DD + warp * 64;
    float q0 = qp[lane], q1 = qp[lane + 32];

    float sc[SS];
    #pragma unroll
    for (int s = 0; s < SS; s++) {
        const float* kp = kv + (long)(s*BB + b) * 1024 + warp * 64;
        float d = q0 * kp[lane] + q1 * kp[lane + 32];
        #pragma unroll
        for (int o = 16; o > 0; o >>= 1) d += __shfl_xor_sync(0xffffffff, d, o);
        sc[s] = d * 0.125f;
    }
    float m = fmaxf(sc[0], fmaxf(sc[1], sc[2]));
    float e[SS], sum = 0.0f;
    #pragma unroll
    for (int s = 0; s < SS; s++) { e[s] = expf(sc[s] - m); sum += e[s]; }
    float inv = 1.0f / sum;

    float c0 = 0.0f, c1 = 0.0f;
    #pragma unroll
    for (int s = 0; s < SS; s++) {
        const float* vp = kv + (long)(s*BB + b) * 1024 + 512 + warp * 64;
        float w = e[s] * inv;
        c0 += w * vp[lane];
        c1 += w * vp[lane + 32];
    }
    ctx[(long)b * DD + warp*64 + lane]      = c0;
    ctx[(long)b * DD + warp*64 + lane + 32] = c1;
}

__global__ void proj_reduce_kernel(const float* __restrict__ part,
                                   const float* __restrict__ bias,
                                   float* __restrict__ out)
{
    int idx = blockIdx.x * blockDim.x + threadIdx.x;
    if (idx >= BB*DD) return;
    int n = idx & 511;
    float v = ((part[idx] + part[BB*DD + idx]) + part[2*BB*DD + idx])
              + part[3*BB*DD + idx] + bias[n];
    out[idx] = v;
}

// ---------------------------------------------------------------------------
extern "C" void kernel_launch(void* const* d_in, const int* in_sizes, int n_in,
                              void* d_out, int out_size)
{
    (void)in_sizes; (void)n_in; (void)out_size;

    const float* x        = (const float*)d_in[0];
    const float* h_prev   = (const float*)d_in[1];
    const float* lstm_h   = (const float*)d_in[2];
    const float* lstm_c   = (const float*)d_in[3];
    const float* A        = (const float*)d_in[4];
    const float* Bm       = (const float*)d_in[5];
    const float* dn_w1    = (const float*)d_in[6];
    const float* dn_b1    = (const float*)d_in[7];
    const float* dn_g     = (const float*)d_in[8];
    const float* dn_beta  = (const float*)d_in[9];
    const float* dn_w2    = (const float*)d_in[10];
    const float* dn_b2    = (const float*)d_in[11];
    const float* lstm_wih = (const float*)d_in[12];
    const float* lstm_whh = (const float*)d_in[13];
    const float* lstm_bih = (const float*)d_in[14];
    const float* lstm_bhh = (const float*)d_in[15];
    const float* decays   = (const float*)d_in[16];
    const float* attn_in_w  = (const float*)d_in[17];
    const float* attn_in_b  = (const float*)d_in[18];
    const float* attn_out_w = (const float*)d_in[19];
    const float* attn_out_b = (const float*)d_in[20];
    const float* proj_w   = (const float*)d_in[21];
    const float* proj_b   = (const float*)d_in[22];
    const float* proj_g   = (const float*)d_in[23];
    const float* proj_beta= (const float*)d_in[24];

    float* out = (float*)d_out;
    float* out_y    = out;
    float* out_hssm = out + BB*DD;
    float* out_hnew = out + 2*BB*DD;
    float* out_cnew = out + 2*BB*DD + SS*BB*DD;

    float *p_h1, *p_delta, *p_bx, *p_T, *p_U, *p_AT, *p_Wpow, *p_part,
          *p_gates, *p_q, *p_kv, *p_ctx, *p_comb, *p_pre;
    cudaGetSymbolAddress((void**)&p_h1,    g_h1);
    cudaGetSymbolAddress((void**)&p_delta, g_delta);
    cudaGetSymbolAddress((void**)&p_bx,    g_bx);
    cudaGetSymbolAddress((void**)&p_T,     g_T);
    cudaGetSymbolAddress((void**)&p_U,     g_U);
    cudaGetSymbolAddress((void**)&p_AT,    g_AT);
    cudaGetSymbolAddress((void**)&p_Wpow,  g_Wpow);
    cudaGetSymbolAddress((void**)&p_part,  g_part);
    cudaGetSymbolAddress((void**)&p_gates, g_gates);
    cudaGetSymbolAddress((void**)&p_q,     g_q);
    cudaGetSymbolAddress((void**)&p_kv,    g_kv);
    cudaGetSymbolAddress((void**)&p_ctx,   g_ctx);
    cudaGetSymbolAddress((void**)&p_comb,  g_comb);
    cudaGetSymbolAddress((void**)&p_pre,   g_pre);

    cudaFuncSetAttribute(gemm_tc, cudaFuncAttributeMaxDynamicSharedMemorySize, SM_TOTAL);

    #define NO2 nullptr, 0L, 0, nullptr, 0L, 0
    #define NOSPLIT nullptr, nullptr, 0, nullptr, (1<<30)

    // ---- 0. AT = A^T ; Wpow[0:512] = A ----
    transpose_copy_kernel<<<dim3(16,16), dim3(32,8)>>>(A, p_AT, p_Wpow);

    // ---- 1. matrix powers: A^2, A^3, A^4 (each = prev @ AT^T) ----
    gemm_tc<<<dim3(4,4,1), 256, SM_TOTAL>>>(
        A, 0L, DD,  p_AT, 0L, DD,  NO2,
        p_Wpow + (long)DD*DD, 0L, DD,  DD,
        nullptr, 0L, nullptr, 0L,  NOSPLIT);
    gemm_tc<<<dim3(4,4,1), 256, SM_TOTAL>>>(
        p_Wpow + (long)DD*DD, 0L, DD,  p_AT, 0L, DD,  NO2,
        p_Wpow + 2L*DD*DD, 0L, DD,  DD,
        nullptr, 0L, nullptr, 0L,  NOSPLIT);
    gemm_tc<<<dim3(4,4,1), 256, SM_TOTAL>>>(
        p_Wpow + 2L*DD*DD, 0L, DD,  p_AT, 0L, DD,  NO2,
        p_Wpow + 3L*DD*DD, 0L, DD,  DD,
        nullptr, 0L, nullptr, 0L,  NOSPLIT);

    // ---- 2. [h1 | bx] = x @ [dn_w1 | Bm]^T ----
    gemm_tc<<<dim3(8,2,1), 256, SM_TOTAL>>>(
        x, 0L, DD,  dn_w1, 0L, DD,  NO2,
        p_h1, 0L, DD,  DD,
        dn_b1, 0L,  nullptr, 0L,
        Bm, p_bx, DD, nullptr, DD);
    ln_act_kernel<<<BB, 256>>>(p_h1, dn_g, dn_beta, p_h1, 1);
    rowdot_softplus_kernel<<<BB, 256>>>(p_h1, dn_w2, dn_b2, p_delta);

    // ---- 3. Taylor chain: 5 iters x 4 terms (KT=20) ----
    cudaMemcpyAsync(out_hssm, h_prev, sizeof(float)*BB*DD, cudaMemcpyDeviceToDevice, 0);
    cudaMemcpyAsync(p_T,      h_prev, sizeof(float)*BB*DD, cudaMemcpyDeviceToDevice, 0);
    for (int it = 0; it < 5; it++) {
        gemm_tc<<<dim3(16,2,1), 256, SM_TOTAL>>>(
            p_T, 0L, DD,  p_Wpow, 0L, DD,  NO2,
            p_U, 0L, 4*DD,  DD,
            nullptr, 0L, nullptr, 0L,  NOSPLIT);
        chain_epilogue_kernel<<<(BB*DD)/256, 256>>>(
            p_U, p_delta, p_T, out_hssm, 4*it, p_bx, p_comb, it == 4);
    }

    // ---- 4. LSTM gates (dual-K) + pointwise ----
    gemm_tc<<<dim3(16,2,SS), 256, SM_TOTAL>>>(
        x, 0L, DD,  lstm_wih, (long)4*DD*DD, DD,
        lstm_h, (long)BB*DD, DD,  lstm_whh, (long)4*DD*DD, DD,
        p_gates, (long)BB*4*DD, 4*DD,  DD,
        lstm_bih, 4*DD,  lstm_bhh, 4*DD,  NOSPLIT);
    lstm_point_kernel<<<(SS*BB*DD)/256, 256>>>(
        p_gates, lstm_c, decays, out_hnew, out_cnew, p_comb);

    // ---- 5. [k|v] = h_new @ [Wk|Wv]^T ----
    gemm_tc<<<dim3(8,6,1), 256, SM_TOTAL>>>(
        out_hnew, 0L, DD,  attn_in_w + (long)DD*DD, 0L, DD,  NO2,
        p_kv, 0L, 2*DD,  DD,
        attn_in_b + DD, 0L,  nullptr, 0L,  NOSPLIT);

    // ---- 6. q = h_ssm @ Wq^T ----
    gemm_tc<<<dim3(4,2,1), 256, SM_TOTAL>>>(
        out_hssm, 0L, DD,  attn_in_w, 0L, DD,  NO2,
        p_q, 0L, DD,  DD,
        attn_in_b, 0L,  nullptr, 0L,  NOSPLIT);

    // ---- 7. attention ----
    attn_kernel<<<BB, 256>>>(p_q, p_kv, p_ctx);

    // ---- 8. fused = ctx @ attn_out_w^T + b -> comb[:,512:1024] ----
    gemm_tc<<<dim3(4,2,1), 256, SM_TOTAL>>>(
        p_ctx, 0L, DD,  attn_out_w, 0L, DD,  NO2,
        p_comb + DD, 0L, 5*DD,  DD,
        attn_out_b, 0L,  nullptr, 0L,  NOSPLIT);

    // ---- 9. proj (K=2560) split-K=4 over z ----
    gemm_tc<<<dim3(4,2,4), 256, SM_TOTAL>>>(
        p_comb, 640L, 5*DD,  proj_w, 640L, 5*DD,  NO2,
        p_part, (long)BB*DD, DD,  640,
        nullptr, 0L,  nullptr, 0L,  NOSPLIT);
    proj_reduce_kernel<<<(BB*DD + 255)/256, 256>>>(p_part, proj_b, p_pre);
    ln_act_kernel<<<BB, 256>>>(p_pre, proj_g, proj_beta, out_y, 0);
}

// round 5
// speedup vs baseline: 1.5606x; 1.0517x over previous
#include <cuda_runtime.h>
#include <cuda_bf16.h>
#include <math.h>
#include <cstdint>

// ---------------------------------------------------------------------------
// SSMXLSTMFusion: D=512, S=3, BATCH=256, H=8, HD=64
// Round 5: task-batched mma.sync GEMM with register prefetch pipelining and
// ldmatrix fragment loads. bf16 hi/lo emulated fp32 (3 cross products).
// Taylor chain via A^1..A^4 stacked weights, 5 iterations (KT=20).
// ---------------------------------------------------------------------------

#define DD    512
#define BB    256
#define SS    3

// ------------------------- scratch (device globals) ------------------------
__device__ float g_h1   [BB*DD];
__device__ float g_delta[BB];
__device__ float g_bx   [BB*DD];
__device__ float g_T    [BB*DD];
__device__ float g_U    [BB*4*DD];
__device__ float g_AT   [DD*DD];
__device__ float g_A2T  [DD*DD];
__device__ float g_Wpow [4*DD*DD];
__device__ float g_part [4*BB*DD];
__device__ float g_gates[SS*BB*4*DD];
__device__ float g_q    [BB*DD];
__device__ float g_kv   [SS*BB*2*DD];
__device__ float g_ctx  [BB*DD];
__device__ float g_comb [BB*5*DD];

// ========================= task descriptor ==================================
struct GTask {
    const float *X, *X2, *W, *W2, *Wn2;
    const float *bias, *bias2, *biasn2;
    float *C, *Cn2, *Ct;
    int ldX, ldX2, ldW, ldW2, ldC, ldCn2, ldCt;
    int K, nsplit, mtiles, blocks;
};
struct GTaskSet { GTask t[6]; int ntasks; };

#define NOSPLIT (1<<30)

// ========================= smem layout ======================================
#define RSB   80                // 32 bf16 (64B) + 16B pad; mult of 16
#define PLANE (128*RSB)         // 10240 B
#define OFF_AHI 0
#define OFF_ALO (PLANE)
#define OFF_BHI (2*PLANE)
#define OFF_BLO (3*PLANE)
// total static smem: 40960 B

__device__ __forceinline__ uint32_t smem_to_u32(const void* p) {
    uint32_t a;
    asm("{ .reg .u64 t; cvta.to.shared.u64 t, %1; cvt.u32.u64 %0, t; }"
        : "=r"(a) : "l"(p));
    return a;
}

__device__ __forceinline__ uint32_t pkbf(float a, float b) {
    __nv_bfloat16 h0 = __float2bfloat16_rn(a);
    __nv_bfloat16 h1 = __float2bfloat16_rn(b);
    uint16_t u0 = *(uint16_t*)&h0, u1 = *(uint16_t*)&h1;
    return (uint32_t)u0 | ((uint32_t)u1 << 16);
}

// 8 floats -> hi uint4, lo uint4
__device__ __forceinline__ void split8(float4 u, float4 v, uint4& hi, uint4& lo)
{
    float f[8] = {u.x,u.y,u.z,u.w,v.x,v.y,v.z,v.w};
    float r[8];
    uint32_t h[4];
    #pragma unroll
    for (int i = 0; i < 4; i++) {
        __nv_bfloat16 b0 = __float2bfloat16_rn(f[2*i]);
        __nv_bfloat16 b1 = __float2bfloat16_rn(f[2*i+1]);
        r[2*i]   = f[2*i]   - __bfloat162float(b0);
        r[2*i+1] = f[2*i+1] - __bfloat162float(b1);
        uint16_t u0 = *(uint16_t*)&b0, u1 = *(uint16_t*)&b1;
        h[i] = (uint32_t)u0 | ((uint32_t)u1 << 16);
    }
    hi = make_uint4(h[0], h[1], h[2], h[3]);
    lo = make_uint4(pkbf(r[0],r[1]), pkbf(r[2],r[3]),
                    pkbf(r[4],r[5]), pkbf(r[6],r[7]));
}

__device__ __forceinline__ void ldm_x4(uint32_t* r, uint32_t addr) {
    asm volatile("ldmatrix.sync.aligned.m8n8.x4.shared.b16 {%0,%1,%2,%3}, [%4];"
        : "=r"(r[0]), "=r"(r[1]), "=r"(r[2]), "=r"(r[3]) : "r"(addr));
}

__device__ __forceinline__ void mma_bf16(float* c, const uint32_t* a, const uint32_t* b)
{
    asm volatile(
        "mma.sync.aligned.m16n8k16.row.col.f32.bf16.bf16.f32 "
        "{%0,%1,%2,%3}, {%4,%5,%6,%7}, {%8,%9}, {%0,%1,%2,%3};"
        : "+f"(c[0]), "+f"(c[1]), "+f"(c[2]), "+f"(c[3])
        : "r"(a[0]), "r"(a[1]), "r"(a[2]), "r"(a[3]), "r"(b[0]), "r"(b[1]));
}

// ========================= GEMM kernel ======================================
// Each block: one 128x128 tile of one task. 256 threads (8 warps, 4m x 2n).
// K consumed in 32-wide chunks with register prefetch of the next chunk.
__global__ void __launch_bounds__(256, 1)
gemm_mma(GTaskSet ts)
{
    __shared__ char smem[4*PLANE];

    // ---- find task ----
    int b = blockIdx.x, ti = 0;
    while (b >= ts.t[ti].blocks) { b -= ts.t[ti].blocks; ti++; }
    const GTask T = ts.t[ti];
    const int mt_ = b % T.mtiles;
    const int nt_ = b / T.mtiles;
    const int m0 = mt_ * 128;
    const int n0 = nt_ * 128;

    const int tid = threadIdx.x;
    const int lid = tid & 31;
    const int wid = tid >> 5;
    const int m_base = (wid & 3) * 32;
    const int n_base = (wid >> 2) * 64;
    const int gid = lid >> 2;
    const int tig = lid & 3;
    const int g  = lid >> 3;
    const int ig = lid & 7;

    const uint32_t sm = smem_to_u32(smem);
    // ldmatrix base addresses (per-lane)
    const uint32_t a_ad = sm + (uint32_t)((m_base + (g&1)*8 + ig) * RSB + (g>>1)*16);
    const uint32_t b_ad = sm + (uint32_t)((n_base + (g>>1)*8 + ig) * RSB + (g&1)*16);

    float acc[2][8][4];
    #pragma unroll
    for (int i = 0; i < 2; i++)
        #pragma unroll
        for (int j = 0; j < 8; j++)
            #pragma unroll
            for (int k = 0; k < 4; k++) acc[i][j][k] = 0.0f;

    const int cpp = T.K >> 5;            // chunks per pass
    const int nchunks = T.X2 ? 2*cpp : cpp;

    // loader: threads 0..127 -> A row tid; 128..255 -> B row tid-128
    const int lr = tid & 127;
    const bool isA = tid < 128;

    float4 pf[8];
    // prefetch chunk 0
    {
        const float* src;
        if (isA) src = T.X + (long)(m0 + lr) * T.ldX;
        else {
            int ng = n0 + lr;
            src = (ng >= T.nsplit) ? T.Wn2 + (long)(ng - T.nsplit) * T.ldW
                                   : T.W   + (long)ng * T.ldW;
        }
        #pragma unroll
        for (int j = 0; j < 8; j++) pf[j] = ((const float4*)src)[j];
    }

    char* ph = smem + (isA ? OFF_AHI : OFF_BHI) + lr * RSB;
    char* pl = smem + (isA ? OFF_ALO : OFF_BLO) + lr * RSB;

    for (int c = 0; c < nchunks; c++) {
        __syncthreads();
        // store current chunk to smem (hi/lo split)
        #pragma unroll
        for (int j = 0; j < 4; j++) {
            uint4 hi, lo;
            split8(pf[2*j], pf[2*j+1], hi, lo);
            *(uint4*)(ph + j*16) = hi;
            *(uint4*)(pl + j*16) = lo;
        }
        __syncthreads();

        // prefetch next chunk (overlaps with MMA below)
        if (c + 1 < nchunks) {
            int cn = c + 1;
            int pass = cn / cpp;
            int k0 = (cn - pass*cpp) * 32;
            const float* src;
            if (isA) {
                const float* Xp = pass ? T.X2 : T.X;
                int ldx = pass ? T.ldX2 : T.ldX;
                src = Xp + (long)(m0 + lr) * ldx + k0;
            } else {
                int ng = n0 + lr;
                const float* Wp = pass ? T.W2 : T.W;
                int ldw = pass ? T.ldW2 : T.ldW;
                const float* row = (!pass && ng >= T.nsplit)
                                 ? T.Wn2 + (long)(ng - T.nsplit) * ldw
                                 : Wp    + (long)ng * ldw;
                src = row + k0;
            }
            #pragma unroll
            for (int j = 0; j < 8; j++) pf[j] = ((const float4*)src)[j];
        }

        // ---- MMA over this chunk: 2 k-steps of 16 ----
        #pragma unroll
        for (int ks = 0; ks < 2; ks++) {
            const uint32_t kb = ks * 32;
            uint32_t ahi[2][4], alo[2][4], bhi[8][2], blo[8][2];
            #pragma unroll
            for (int mt = 0; mt < 2; mt++) {
                ldm_x4(ahi[mt], a_ad + OFF_AHI + mt*16*RSB + kb);
                ldm_x4(alo[mt], a_ad + OFF_ALO + mt*16*RSB + kb);
            }
            #pragma unroll
            for (int np = 0; np < 4; np++) {
                uint32_t r[4];
                ldm_x4(r, b_ad + OFF_BHI + np*16*RSB + kb);
                bhi[2*np][0] = r[0]; bhi[2*np][1] = r[1];
                bhi[2*np+1][0] = r[2]; bhi[2*np+1][1] = r[3];
                ldm_x4(r, b_ad + OFF_BLO + np*16*RSB + kb);
                blo[2*np][0] = r[0]; blo[2*np][1] = r[1];
                blo[2*np+1][0] = r[2]; blo[2*np+1][1] = r[3];
            }
            #pragma unroll
            for (int mt = 0; mt < 2; mt++)
                #pragma unroll
                for (int nt = 0; nt < 8; nt++) {
                    mma_bf16(acc[mt][nt], ahi[mt], bhi[nt]);
                    mma_bf16(acc[mt][nt], ahi[mt], blo[nt]);
                    mma_bf16(acc[mt][nt], alo[mt], bhi[nt]);
                }
        }
    }

    // ---- epilogue ----
    #pragma unroll
    for (int mt = 0; mt < 2; mt++) {
        #pragma unroll
        for (int nt = 0; nt < 8; nt++) {
            int n = n0 + n_base + nt*8 + tig*2;
            #pragma unroll
            for (int half = 0; half < 2; half++) {
                int mm = m0 + m_base + mt*16 + gid + half*8;
                float v0 = acc[mt][nt][half*2];
                float v1 = acc[mt][nt][half*2 + 1];
                if (T.Cn2 && n >= T.nsplit) {
                    int nn = n - T.nsplit;
                    if (T.biasn2) { v0 += T.biasn2[nn]; v1 += T.biasn2[nn+1]; }
                    float2* dst = (float2*)(T.Cn2 + (long)mm*T.ldCn2 + nn);
                    *dst = make_float2(v0, v1);
                } else {
                    if (T.bias)  { v0 += T.bias[n];  v1 += T.bias[n+1]; }
                    if (T.bias2) { v0 += T.bias2[n]; v1 += T.bias2[n+1]; }
                    float2* dst = (float2*)(T.C + (long)mm*T.ldC + n);
                    *dst = make_float2(v0, v1);
                    if (T.Ct) {
                        T.Ct[(long)n*T.ldCt + mm]     = v0;
                        T.Ct[(long)(n+1)*T.ldCt + mm] = v1;
                    }
                }
            }
        }
    }
}

// ========================= small SIMT kernels ===============================
__global__ void transpose_copy_kernel(const float* __restrict__ A,
                                      float* __restrict__ AT,
                                      float* __restrict__ W0)
{
    __shared__ float t[32][33];
    int bx = blockIdx.x*32, by = blockIdx.y*32;
    int x = bx + threadIdx.x;
    #pragma unroll
    for (int i = 0; i < 32; i += 8) {
        int y = by + threadIdx.y + i;
        float v = A[(long)y*DD + x];
        t[threadIdx.y + i][threadIdx.x] = v;
        W0[(long)y*DD + x] = v;
    }
    __syncthreads();
    int xo = by + threadIdx.x;
    #pragma unroll
    for (int i = 0; i < 32; i += 8) {
        int yo = bx + threadIdx.y + i;
        AT[(long)yo*DD + xo] = t[threadIdx.x][threadIdx.y + i];
    }
}

// fused: LN(h1)+gelu -> dot(w2) -> softplus -> delta  (h1 not written back)
__global__ void delta_kernel(const float* __restrict__ h1,
                             const float* __restrict__ g,
                             const float* __restrict__ b,
                             const float* __restrict__ w2,
                             const float* __restrict__ b2,
                             float* __restrict__ delta)
{
    __shared__ float red[256];
    int row = blockIdx.x, t = threadIdx.x;
    const float* r = h1 + (long)row * DD;
    float x0 = r[t], x1 = r[t + 256];

    red[t] = x0 + x1; __syncthreads();
    for (int o = 128; o > 0; o >>= 1) { if (t < o) red[t] += red[t+o]; __syncthreads(); }
    float mean = red[0] * (1.0f/DD);
    __syncthreads();

    float d0 = x0 - mean, d1 = x1 - mean;
    red[t] = d0*d0 + d1*d1; __syncthreads();
    for (int o = 128; o > 0; o >>= 1) { if (t < o) red[t] += red[t+o]; __syncthreads(); }
    float inv = rsqrtf(red[0] * (1.0f/DD) + 1e-5f);
    __syncthreads();

    float y0 = d0 * inv * g[t]     + b[t];
    float y1 = d1 * inv * g[t+256] + b[t+256];
    y0 = 0.5f * y0 * (1.0f + erff(y0 * 0.70710678118654752f));
    y1 = 0.5f * y1 * (1.0f + erff(y1 * 0.70710678118654752f));

    red[t] = y0*w2[t] + y1*w2[t+256]; __syncthreads();
    for (int o = 128; o > 0; o >>= 1) { if (t < o) red[t] += red[t+o]; __syncthreads(); }
    if (t == 0) {
        float z = red[0] + b2[0];
        delta[row] = (z > 20.0f) ? z : log1pf(expf(z));
    }
}

// chain epilogue: U[b, j*512+n] = (A^{j+1} t_{k0})[n], j=0..3
__global__ void chain_epilogue_kernel(const float* __restrict__ U,
                                      const float* __restrict__ delta,
                                      float* __restrict__ T,
                                      float* __restrict__ y,
                                      const float* __restrict__ h_prev,
                                      int k0,
                                      const float* __restrict__ bx,
                                      float* __restrict__ comb,
                                      int last)
{
    int idx = blockIdx.x * blockDim.x + threadIdx.x;
    if (idx >= BB*DD) return;
    int b = idx >> 9, n = idx & 511;
    float d  = delta[b];
    float c1 = d / (float)(k0+1);
    float c2 = c1 * d / (float)(k0+2);
    float c3 = c2 * d / (float)(k0+3);
    float c4 = c3 * d / (float)(k0+4);
    const float* ub = U + (long)b * 2048;
    float t4 = c4 * ub[1536 + n];
    float yprev = (k0 == 0) ? h_prev[idx] : y[idx];
    float yy = yprev + c1*ub[n] + c2*ub[512+n] + c3*ub[1024+n] + t4;
    if (last) {
        yy += d * bx[idx];
        comb[(long)b*2560 + n] = yy;
    }
    y[idx] = yy;
    T[idx] = t4;
}

__device__ __forceinline__ float sigf(float x) { return 1.0f / (1.0f + expf(-x)); }

__global__ void lstm_point_kernel(const float* __restrict__ gates,
                                  const float* __restrict__ lstm_c,
                                  const float* __restrict__ decays,
                                  float* __restrict__ h_new,
                                  float* __restrict__ c_new,
                                  float* __restrict__ comb)
{
    int idx = blockIdx.x * blockDim.x + threadIdx.x;
    if (idx >= SS*BB*DD) return;
    int s = idx / (BB*DD);
    int r = idx - s * (BB*DD);
    int b = r >> 9;
    int d = r & 511;
    const float* gp = gates + ((long)s * BB + b) * (4*DD);
    float i_g = sigf(gp[d]);
    float f_g = sigf(gp[DD + d]);
    float g_g = tanhf(gp[2*DD + d]);
    float o_g = sigf(gp[3*DD + d]);
    float c   = lstm_c[idx];
    float craw = f_g * c + i_g * g_g;
    float hn   = o_g * tanhf(craw);
    float dec  = decays[s];
    h_new[idx] = hn;
    c_new[idx] = dec * c + (1.0f - dec) * craw;
    comb[(long)b * 2560 + 1024 + s*512 + d] = hn;
}

__global__ void attn_kernel(const float* __restrict__ q,
                            const float* __restrict__ kv,
                            float* __restrict__ ctx)
{
    int b    = blockIdx.x;
    int warp = threadIdx.x >> 5;
    int lane = threadIdx.x & 31;

    const float* qp = q + (long)b * DD + warp * 64;
    float q0 = qp[lane], q1 = qp[lane + 32];

    float sc[SS];
    #pragma unroll
    for (int s = 0; s < SS; s++) {
        const float* kp = kv + (long)(s*BB + b) * 1024 + warp * 64;
        float d = q0 * kp[lane] + q1 * kp[lane + 32];
        #pragma unroll
        for (int o = 16; o > 0; o >>= 1) d += __shfl_xor_sync(0xffffffff, d, o);
        sc[s] = d * 0.125f;
    }
    float m = fmaxf(sc[0], fmaxf(sc[1], sc[2]));
    float e[SS], sum = 0.0f;
    #pragma unroll
    for (int s = 0; s < SS; s++) { e[s] = expf(sc[s] - m); sum += e[s]; }
    float inv = 1.0f / sum;

    float c0 = 0.0f, c1 = 0.0f;
    #pragma unroll
    for (int s = 0; s < SS; s++) {
        const float* vp = kv + (long)(s*BB + b) * 1024 + 512 + warp * 64;
        float w = e[s] * inv;
        c0 += w * vp[lane];
        c1 += w * vp[lane + 32];
    }
    ctx[(long)b * DD + warp*64 + lane]      = c0;
    ctx[(long)b * DD + warp*64 + lane + 32] = c1;
}

// fused: sum 4 split-K partials + bias -> layernorm -> out
__global__ void proj_ln_kernel(const float* __restrict__ part,
                               const float* __restrict__ bias,
                               const float* __restrict__ g,
                               const float* __restrict__ be,
                               float* __restrict__ out)
{
    __shared__ float red[256];
    int row = blockIdx.x, t = threadIdx.x;
    long o0 = (long)row*DD + t, o1 = o0 + 256;
    float x0 = ((part[o0] + part[BB*DD + o0]) + part[2*BB*DD + o0])
               + part[3*BB*DD + o0] + bias[t];
    float x1 = ((part[o1] + part[BB*DD + o1]) + part[2*BB*DD + o1])
               + part[3*BB*DD + o1] + bias[t+256];

    red[t] = x0 + x1; __syncthreads();
    for (int o = 128; o > 0; o >>= 1) { if (t < o) red[t] += red[t+o]; __syncthreads(); }
    float mean = red[0] * (1.0f/DD);
    __syncthreads();

    float d0 = x0 - mean, d1 = x1 - mean;
    red[t] = d0*d0 + d1*d1; __syncthreads();
    for (int o = 128; o > 0; o >>= 1) { if (t < o) red[t] += red[t+o]; __syncthreads(); }
    float inv = rsqrtf(red[0] * (1.0f/DD) + 1e-5f);

    out[o0] = d0 * inv * g[t]     + be[t];
    out[o1] = d1 * inv * g[t+256] + be[t+256];
}

// ---------------------------------------------------------------------------
static inline GTask mk_task(const float* X, int ldX, const float* W, int ldW,
                            float* C, int ldC, int K, int mtiles, int ntiles)
{
    GTask t = {};
    t.X = X; t.ldX = ldX; t.W = W; t.ldW = ldW; t.C = C; t.ldC = ldC;
    t.K = K; t.nsplit = NOSPLIT; t.mtiles = mtiles; t.blocks = mtiles*ntiles;
    return t;
}

extern "C" void kernel_launch(void* const* d_in, const int* in_sizes, int n_in,
                              void* d_out, int out_size)
{
    (void)in_sizes; (void)n_in; (void)out_size;

    const float* x        = (const float*)d_in[0];
    const float* h_prev   = (const float*)d_in[1];
    const float* lstm_h   = (const float*)d_in[2];
    const float* lstm_c   = (const float*)d_in[3];
    const float* A        = (const float*)d_in[4];
    const float* Bm       = (const float*)d_in[5];
    const float* dn_w1    = (const float*)d_in[6];
    const float* dn_b1    = (const float*)d_in[7];
    const float* dn_g     = (const float*)d_in[8];
    const float* dn_beta  = (const float*)d_in[9];
    const float* dn_w2    = (const float*)d_in[10];
    const float* dn_b2    = (const float*)d_in[11];
    const float* lstm_wih = (const float*)d_in[12];
    const float* lstm_whh = (const float*)d_in[13];
    const float* lstm_bih = (const float*)d_in[14];
    const float* lstm_bhh = (const float*)d_in[15];
    const float* decays   = (const float*)d_in[16];
    const float* attn_in_w  = (const float*)d_in[17];
    const float* attn_in_b  = (const float*)d_in[18];
    const float* attn_out_w = (const float*)d_in[19];
    const float* attn_out_b = (const float*)d_in[20];
    const float* proj_w   = (const float*)d_in[21];
    const float* proj_b   = (const float*)d_in[22];
    const float* proj_g   = (const float*)d_in[23];
    const float* proj_beta= (const float*)d_in[24];

    float* out = (float*)d_out;
    float* out_y    = out;
    float* out_hssm = out + BB*DD;
    float* out_hnew = out + 2*BB*DD;
    float* out_cnew = out + 2*BB*DD + SS*BB*DD;

    float *p_h1, *p_delta, *p_bx, *p_T, *p_U, *p_AT, *p_A2T, *p_Wpow,
          *p_part, *p_gates, *p_q, *p_kv, *p_ctx, *p_comb;
    cudaGetSymbolAddress((void**)&p_h1,    g_h1);
    cudaGetSymbolAddress((void**)&p_delta, g_delta);
    cudaGetSymbolAddress((void**)&p_bx,    g_bx);
    cudaGetSymbolAddress((void**)&p_T,     g_T);
    cudaGetSymbolAddress((void**)&p_U,     g_U);
    cudaGetSymbolAddress((void**)&p_AT,    g_AT);
    cudaGetSymbolAddress((void**)&p_A2T,   g_A2T);
    cudaGetSymbolAddress((void**)&p_Wpow,  g_Wpow);
    cudaGetSymbolAddress((void**)&p_part,  g_part);
    cudaGetSymbolAddress((void**)&p_gates, g_gates);
    cudaGetSymbolAddress((void**)&p_q,     g_q);
    cudaGetSymbolAddress((void**)&p_kv,    g_kv);
    cudaGetSymbolAddress((void**)&p_ctx,   g_ctx);
    cudaGetSymbolAddress((void**)&p_comb,  g_comb);

    // ---- 0. AT = A^T ; Wpow[0] = A ----
    transpose_copy_kernel<<<dim3(16,16), dim3(32,8)>>>(A, p_AT, p_Wpow);

    // ---- G1: h1|bx, gates s=0..2, A^2 (+A^2T) ----
    {
        GTaskSet ts = {};
        // h1|bx: x @ [dn_w1|Bm]^T, N=1024 split at 512
        GTask t0 = mk_task(x, DD, dn_w1, DD, p_h1, DD, DD, 2, 8);
        t0.bias = dn_b1; t0.Wn2 = Bm; t0.Cn2 = p_bx; t0.ldCn2 = DD; t0.nsplit = DD;
        ts.t[0] = t0;
        for (int s = 0; s < SS; s++) {
            GTask tg = mk_task(x, DD, lstm_wih + (long)s*4*DD*DD, DD,
                               p_gates + (long)s*BB*4*DD, 4*DD, DD, 2, 16);
            tg.X2 = lstm_h + (long)s*BB*DD; tg.ldX2 = DD;
            tg.W2 = lstm_whh + (long)s*4*DD*DD; tg.ldW2 = DD;
            tg.bias  = lstm_bih + (long)s*4*DD;
            tg.bias2 = lstm_bhh + (long)s*4*DD;
            ts.t[1+s] = tg;
        }
        GTask ta = mk_task(A, DD, p_AT, DD, p_Wpow + (long)DD*DD, DD, DD, 4, 4);
        ta.Ct = p_A2T; ta.ldCt = DD;
        ts.t[4] = ta;
        ts.ntasks = 5;
        gemm_mma<<<128, 256>>>(ts);
    }

    // ---- delta + lstm pointwise ----
    delta_kernel<<<BB, 256>>>(p_h1, dn_g, dn_beta, dn_w2, dn_b2, p_delta);
    lstm_point_kernel<<<(SS*BB*DD)/256, 256>>>(
        p_gates, lstm_c, decays, out_hnew, out_cnew, p_comb);

    // ---- G2: A^3 = A @ (A^2T)^T, A^4 = A^2 @ (A^2T)^T ----
    {
        GTaskSet ts = {};
        ts.t[0] = mk_task(A, DD, p_A2T, DD, p_Wpow + 2L*DD*DD, DD, DD, 4, 4);
        ts.t[1] = mk_task(p_Wpow + (long)DD*DD, DD, p_A2T, DD,
                          p_Wpow + 3L*DD*DD, DD, DD, 4, 4);
        ts.ntasks = 2;
        gemm_mma<<<32, 256>>>(ts);
    }

    // ---- Taylor chain: 5 iters x 4 terms (KT=20) ----
    for (int it = 0; it < 5; it++) {
        GTaskSet ts = {};
        ts.t[0] = mk_task(it == 0 ? h_prev : p_T, DD, p_Wpow, DD,
                          p_U, 4*DD, DD, 2, 16);
        ts.ntasks = 1;
        gemm_mma<<<32, 256>>>(ts);
        chain_epilogue_kernel<<<(BB*DD)/256, 256>>>(
            p_U, p_delta, p_T, out_hssm, h_prev, 4*it, p_bx, p_comb, it == 4);
    }

    // ---- G8: kv (h_new @ [Wk|Wv]^T) + q (h_ssm @ Wq^T) ----
    {
        GTaskSet ts = {};
        GTask tkv = mk_task(out_hnew, DD, attn_in_w + (long)DD*DD, DD,
                            p_kv, 2*DD, DD, 6, 8);
        tkv.bias = attn_in_b + DD;
        ts.t[0] = tkv;
        GTask tq = mk_task(out_hssm, DD, attn_in_w, DD, p_q, DD, DD, 2, 4);
        tq.bias = attn_in_b;
        ts.t[1] = tq;
        ts.ntasks = 2;
        gemm_mma<<<56, 256>>>(ts);
    }

    // ---- attention ----
    attn_kernel<<<BB, 256>>>(p_q, p_kv, p_ctx);

    // ---- fused = ctx @ attn_out_w^T + b -> comb[:,512:1024] ----
    {
        GTaskSet ts = {};
        GTask tf = mk_task(p_ctx, DD, attn_out_w, DD, p_comb + DD, 5*DD, DD, 2, 4);
        tf.bias = attn_out_b;
        ts.t[0] = tf;
        ts.ntasks = 1;
        gemm_mma<<<8, 256>>>(ts);
    }

    // ---- proj split-K=4 (4 tasks) ----
    {
        GTaskSet ts = {};
        for (int j = 0; j < 4; j++)
            ts.t[j] = mk_task(p_comb + j*640, 5*DD, proj_w + j*640, 5*DD,
                              p_part + (long)j*BB*DD, DD, 640, 2, 4);
        ts.ntasks = 4;
        gemm_mma<<<32, 256>>>(ts);
    }

    // ---- reduce + bias + LN -> out_y ----
    proj_ln_kernel<<<BB, 256>>>(p_part, proj_b, proj_g, proj_beta, out_y);
}

// round 6
// speedup vs baseline: 3.6449x; 2.3355x over previous
#include <cuda_runtime.h>
#include <cuda_bf16.h>
#include <math.h>
#include <cstdint>

// ---------------------------------------------------------------------------
// SSMXLSTMFusion: D=512, S=3, BATCH=256, H=8, HD=64
// Round 6: coalesced GEMM loads (4 threads/row), split-K everywhere for chip
// fill, fused GEMM removed algebraically (M = P1 @ attn_out_w), no comb.
// bf16 hi/lo emulated fp32 mma.sync, Taylor chain A^1..A^4 (KT=20).
// ---------------------------------------------------------------------------

#define DD    512
#define BB    256
#define SS    3

// ------------------------- scratch (device globals) ------------------------
__device__ float g_h1   [BB*DD];
__device__ float g_delta[BB];
__device__ float g_bx   [BB*DD];
__device__ float g_T    [BB*DD];
__device__ float g_U    [4*BB*4*DD];          // 4 split-K planes of [256,2048]
__device__ float g_AT   [DD*DD];
__device__ float g_A2T  [DD*DD];
__device__ float g_AoT  [DD*DD];
__device__ float g_M    [DD*DD];
__device__ float g_Wpow [4*DD*DD];
__device__ float g_gA   [SS*BB*4*DD];
__device__ float g_gB   [SS*BB*4*DD];
__device__ float g_kvp  [2*SS*BB*2*DD];
__device__ float g_qp   [2*BB*DD];
__device__ float g_q    [BB*DD];
__device__ float g_kv   [SS*BB*2*DD];
__device__ float g_ctx  [BB*DD];
__device__ float g_part [10*BB*DD];
__device__ float g_pvec [DD];

// ========================= task descriptor ==================================
struct GTask {
    const float *X, *W, *Wn2, *bias;
    float *C, *Cn2, *Ct;
    int ldX, ldW, ldC, ldCn2, ldCt;
    int K, kofs, nsplit, mtiles, blocks;
};
struct GTaskSet { GTask t[12]; int ntasks; };

#define NOSPLIT (1<<30)

// ========================= smem layout ======================================
#define RSB   80                // 32 bf16 (64B) + 16B pad
#define PLANE (128*RSB)         // 10240 B
#define OFF_AHI 0
#define OFF_ALO (PLANE)
#define OFF_BHI (2*PLANE)
#define OFF_BLO (3*PLANE)

__device__ __forceinline__ uint32_t smem_to_u32(const void* p) {
    uint32_t a;
    asm("{ .reg .u64 t; cvta.to.shared.u64 t, %1; cvt.u32.u64 %0, t; }"
        : "=r"(a) : "l"(p));
    return a;
}

__device__ __forceinline__ uint32_t pkbf(float a, float b) {
    __nv_bfloat16 h0 = __float2bfloat16_rn(a);
    __nv_bfloat16 h1 = __float2bfloat16_rn(b);
    uint16_t u0 = *(uint16_t*)&h0, u1 = *(uint16_t*)&h1;
    return (uint32_t)u0 | ((uint32_t)u1 << 16);
}

__device__ __forceinline__ void split8(float4 u, float4 v, uint4& hi, uint4& lo)
{
    float f[8] = {u.x,u.y,u.z,u.w,v.x,v.y,v.z,v.w};
    float r[8];
    uint32_t h[4];
    #pragma unroll
    for (int i = 0; i < 4; i++) {
        __nv_bfloat16 b0 = __float2bfloat16_rn(f[2*i]);
        __nv_bfloat16 b1 = __float2bfloat16_rn(f[2*i+1]);
        r[2*i]   = f[2*i]   - __bfloat162float(b0);
        r[2*i+1] = f[2*i+1] - __bfloat162float(b1);
        uint16_t u0 = *(uint16_t*)&b0, u1 = *(uint16_t*)&b1;
        h[i] = (uint32_t)u0 | ((uint32_t)u1 << 16);
    }
    hi = make_uint4(h[0], h[1], h[2], h[3]);
    lo = make_uint4(pkbf(r[0],r[1]), pkbf(r[2],r[3]),
                    pkbf(r[4],r[5]), pkbf(r[6],r[7]));
}

__device__ __forceinline__ void ldm_x4(uint32_t* r, uint32_t addr) {
    asm volatile("ldmatrix.sync.aligned.m8n8.x4.shared.b16 {%0,%1,%2,%3}, [%4];"
        : "=r"(r[0]), "=r"(r[1]), "=r"(r[2]), "=r"(r[3]) : "r"(addr));
}

__device__ __forceinline__ void mma_bf16(float* c, const uint32_t* a, const uint32_t* b)
{
    asm volatile(
        "mma.sync.aligned.m16n8k16.row.col.f32.bf16.bf16.f32 "
        "{%0,%1,%2,%3}, {%4,%5,%6,%7}, {%8,%9}, {%0,%1,%2,%3};"
        : "+f"(c[0]), "+f"(c[1]), "+f"(c[2]), "+f"(c[3])
        : "r"(a[0]), "r"(a[1]), "r"(a[2]), "r"(a[3]), "r"(b[0]), "r"(b[1]));
}

// coalesced prefetch: 4 threads per row, each thread a 32B slice; 4 row-groups
__device__ __forceinline__ void prefetch_op(const GTask& T, bool isA,
    int lrow0, int lcb, int m0, int n0, int k0, float4* pf)
{
    if (isA) {
        const float* base = T.X + (long)(m0 + lrow0) * T.ldX + k0 + lcb;
        #pragma unroll
        for (int j = 0; j < 4; j++) {
            const float* src = base + (long)(j*32) * T.ldX;
            pf[2*j]   = *(const float4*)(src);
            pf[2*j+1] = *(const float4*)(src + 4);
        }
    } else {
        #pragma unroll
        for (int j = 0; j < 4; j++) {
            int ng = n0 + j*32 + lrow0;
            const float* row = (ng >= T.nsplit)
                ? T.Wn2 + (long)(ng - T.nsplit) * T.ldW
                : T.W   + (long)ng * T.ldW;
            const float* src = row + k0 + lcb;
            pf[2*j]   = *(const float4*)(src);
            pf[2*j+1] = *(const float4*)(src + 4);
        }
    }
}

// ========================= GEMM kernel ======================================
__global__ void __launch_bounds__(256, 1)
gemm_mma(GTaskSet ts)
{
    __shared__ char smem[4*PLANE];

    int b = blockIdx.x, ti = 0;
    while (b >= ts.t[ti].blocks) { b -= ts.t[ti].blocks; ti++; }
    const GTask T = ts.t[ti];
    const int m0 = (b % T.mtiles) * 128;
    const int n0 = (b / T.mtiles) * 128;

    const int tid = threadIdx.x;
    const int lid = tid & 31;
    const int wid = tid >> 5;
    const int m_base = (wid & 3) * 32;
    const int n_base = (wid >> 2) * 64;
    const int gid = lid >> 2;
    const int tig = lid & 3;
    const int g  = lid >> 3;
    const int ig = lid & 7;

    const uint32_t sm = smem_to_u32(smem);
    const uint32_t a_ad = sm + (uint32_t)((m_base + (g&1)*8 + ig) * RSB + (g>>1)*16);
    const uint32_t b_ad = sm + (uint32_t)((n_base + (g>>1)*8 + ig) * RSB + (g&1)*16);

    float acc[2][8][4];
    #pragma unroll
    for (int i = 0; i < 2; i++)
        #pragma unroll
        for (int j = 0; j < 8; j++)
            #pragma unroll
            for (int k = 0; k < 4; k++) acc[i][j][k] = 0.0f;

    const int lr = tid & 127;
    const bool isA = tid < 128;
    const int lrow0 = lr >> 2;          // 0..31
    const int lcb   = (lr & 3) * 8;     // float col: 0,8,16,24

    const int nc = T.K >> 5;
    float4 pf[8];
    prefetch_op(T, isA, lrow0, lcb, m0, n0, T.kofs, pf);

    char* ph = smem + (isA ? OFF_AHI : OFF_BHI) + lrow0 * RSB + lcb * 2;
    char* pl = smem + (isA ? OFF_ALO : OFF_BLO) + lrow0 * RSB + lcb * 2;

    for (int c = 0; c < nc; c++) {
        __syncthreads();
        #pragma unroll
        for (int j = 0; j < 4; j++) {
            uint4 hi, lo;
            split8(pf[2*j], pf[2*j+1], hi, lo);
            *(uint4*)(ph + j*32*RSB) = hi;
            *(uint4*)(pl + j*32*RSB) = lo;
        }
        __syncthreads();
        if (c + 1 < nc)
            prefetch_op(T, isA, lrow0, lcb, m0, n0, T.kofs + (c+1)*32, pf);

        #pragma unroll
        for (int ks = 0; ks < 2; ks++) {
            const uint32_t kb = ks * 32;
            uint32_t ahi[2][4], alo[2][4], bhi[8][2], blo[8][2];
            #pragma unroll
            for (int mt = 0; mt < 2; mt++) {
                ldm_x4(ahi[mt], a_ad + OFF_AHI + mt*16*RSB + kb);
                ldm_x4(alo[mt], a_ad + OFF_ALO + mt*16*RSB + kb);
            }
            #pragma unroll
            for (int np = 0; np < 4; np++) {
                uint32_t r[4];
                ldm_x4(r, b_ad + OFF_BHI + np*16*RSB + kb);
                bhi[2*np][0] = r[0]; bhi[2*np][1] = r[1];
                bhi[2*np+1][0] = r[2]; bhi[2*np+1][1] = r[3];
                ldm_x4(r, b_ad + OFF_BLO + np*16*RSB + kb);
                blo[2*np][0] = r[0]; blo[2*np][1] = r[1];
                blo[2*np+1][0] = r[2]; blo[2*np+1][1] = r[3];
            }
            #pragma unroll
            for (int mt = 0; mt < 2; mt++)
                #pragma unroll
                for (int nt = 0; nt < 8; nt++) {
                    mma_bf16(acc[mt][nt], ahi[mt], bhi[nt]);
                    mma_bf16(acc[mt][nt], ahi[mt], blo[nt]);
                    mma_bf16(acc[mt][nt], alo[mt], bhi[nt]);
                }
        }
    }

    // ---- epilogue ----
    #pragma unroll
    for (int mt = 0; mt < 2; mt++) {
        #pragma unroll
        for (int nt = 0; nt < 8; nt++) {
            int n = n0 + n_base + nt*8 + tig*2;
            #pragma unroll
            for (int half = 0; half < 2; half++) {
                int mm = m0 + m_base + mt*16 + gid + half*8;
                float v0 = acc[mt][nt][half*2];
                float v1 = acc[mt][nt][half*2 + 1];
                if (T.Cn2 && n >= T.nsplit) {
                    int nn = n - T.nsplit;
                    *(float2*)(T.Cn2 + (long)mm*T.ldCn2 + nn) = make_float2(v0, v1);
                } else {
                    if (T.bias) { v0 += T.bias[n]; v1 += T.bias[n+1]; }
                    *(float2*)(T.C + (long)mm*T.ldC + n) = make_float2(v0, v1);
                    if (T.Ct) {
                        T.Ct[(long)n*T.ldCt + mm]     = v0;
                        T.Ct[(long)(n+1)*T.ldCt + mm] = v1;
                    }
                }
            }
        }
    }
}

// ========================= small SIMT kernels ===============================
// z=0: AT=A^T, W0=A copy ; z=1: AoT=attn_out_w^T
__global__ void transpose2_kernel(const float* __restrict__ A,
                                  float* __restrict__ AT,
                                  float* __restrict__ W0,
                                  const float* __restrict__ B,
                                  float* __restrict__ BT)
{
    __shared__ float t[32][33];
    const float* src = blockIdx.z ? B : A;
    float* dst = blockIdx.z ? BT : AT;
    int bx = blockIdx.x*32, by = blockIdx.y*32;
    int x = bx + threadIdx.x;
    #pragma unroll
    for (int i = 0; i < 32; i += 8) {
        int y = by + threadIdx.y + i;
        float v = src[(long)y*DD + x];
        t[threadIdx.y + i][threadIdx.x] = v;
        if (blockIdx.z == 0) W0[(long)y*DD + x] = v;
    }
    __syncthreads();
    int xo = by + threadIdx.x;
    #pragma unroll
    for (int i = 0; i < 32; i += 8) {
        int yo = bx + threadIdx.y + i;
        dst[(long)yo*DD + xo] = t[threadIdx.x][threadIdx.y + i];
    }
}

// fused: LN(h1)+gelu -> dot(w2) -> softplus
__global__ void delta_kernel(const float* __restrict__ h1,
                             const float* __restrict__ g,
                             const float* __restrict__ b,
                             const float* __restrict__ w2,
                             const float* __restrict__ b2,
                             float* __restrict__ delta)
{
    __shared__ float red[256];
    int row = blockIdx.x, t = threadIdx.x;
    const float* r = h1 + (long)row * DD;
    float x0 = r[t], x1 = r[t + 256];

    red[t] = x0 + x1; __syncthreads();
    for (int o = 128; o > 0; o >>= 1) { if (t < o) red[t] += red[t+o]; __syncthreads(); }
    float mean = red[0] * (1.0f/DD);
    __syncthreads();

    float d0 = x0 - mean, d1 = x1 - mean;
    red[t] = d0*d0 + d1*d1; __syncthreads();
    for (int o = 128; o > 0; o >>= 1) { if (t < o) red[t] += red[t+o]; __syncthreads(); }
    float inv = rsqrtf(red[0] * (1.0f/DD) + 1e-5f);
    __syncthreads();

    float y0 = d0 * inv * g[t]     + b[t];
    float y1 = d1 * inv * g[t+256] + b[t+256];
    y0 = 0.5f * y0 * (1.0f + erff(y0 * 0.70710678118654752f));
    y1 = 0.5f * y1 * (1.0f + erff(y1 * 0.70710678118654752f));

    red[t] = y0*w2[t] + y1*w2[t+256]; __syncthreads();
    for (int o = 128; o > 0; o >>= 1) { if (t < o) red[t] += red[t+o]; __syncthreads(); }
    if (t == 0) {
        float z = red[0] + b2[0];
        delta[row] = (z > 20.0f) ? z : log1pf(expf(z));
    }
}

// pvec[n] = proj_b[n] + sum_k proj_w[n, 512+k] * attn_out_b[k]
__global__ void pvec_kernel(const float* __restrict__ proj_w,
                            const float* __restrict__ aob,
                            const float* __restrict__ proj_b,
                            float* __restrict__ pvec)
{
    __shared__ float red[256];
    int row = blockIdx.x, t = threadIdx.x;
    const float* r = proj_w + (long)row * 2560 + 512;
    red[t] = r[t]*aob[t] + r[t+256]*aob[t+256];
    __syncthreads();
    for (int o = 128; o > 0; o >>= 1) { if (t < o) red[t] += red[t+o]; __syncthreads(); }
    if (t == 0) pvec[row] = proj_b[row] + red[0];
}

// chain epilogue with 4 split-K partial planes
__global__ void chain_epilogue_kernel(const float* __restrict__ U,
                                      const float* __restrict__ delta,
                                      float* __restrict__ T,
                                      float* __restrict__ y,
                                      const float* __restrict__ h_prev,
                                      int k0,
                                      const float* __restrict__ bx,
                                      int last)
{
    int idx = blockIdx.x * blockDim.x + threadIdx.x;
    if (idx >= BB*DD) return;
    int b = idx >> 9, n = idx & 511;
    const long PB = (long)BB * 2048;
    const float* u0 = U + (long)b * 2048 + n;
    float u[4];
    #pragma unroll
    for (int j = 0; j < 4; j++) {
        const float* p = u0 + j*512;
        u[j] = ((p[0] + p[PB]) + p[2*PB]) + p[3*PB];
    }
    float d  = delta[b];
    float c1 = d / (float)(k0+1);
    float c2 = c1 * d / (float)(k0+2);
    float c3 = c2 * d / (float)(k0+3);
    float c4 = c3 * d / (float)(k0+4);
    float t4 = c4 * u[3];
    float yprev = (k0 == 0) ? h_prev[idx] : y[idx];
    float yy = yprev + c1*u[0] + c2*u[1] + c3*u[2] + t4;
    if (last) yy += d * bx[idx];
    y[idx] = yy;
    T[idx] = t4;
}

__device__ __forceinline__ float sigf(float x) { return 1.0f / (1.0f + expf(-x)); }

// sums wih/whh partials + biases, then LSTM pointwise
__global__ void lstm_point_kernel(const float* __restrict__ gA,
                                  const float* __restrict__ gB,
                                  const float* __restrict__ bih,
                                  const float* __restrict__ bhh,
                                  const float* __restrict__ lstm_c,
                                  const float* __restrict__ decays,
                                  float* __restrict__ h_new,
                                  float* __restrict__ c_new)
{
    int idx = blockIdx.x * blockDim.x + threadIdx.x;
    if (idx >= SS*BB*DD) return;
    int s = idx / (BB*DD);
    int r = idx - s * (BB*DD);
    int b = r >> 9;
    int d = r & 511;
    long gbase = ((long)s * BB + b) * 2048;
    const float* a = gA + gbase;
    const float* h = gB + gbase;
    const float* bi = bih + s*2048;
    const float* bh = bhh + s*2048;
    float ip = a[d]        + h[d]        + bi[d]        + bh[d];
    float fp = a[512+d]    + h[512+d]    + bi[512+d]    + bh[512+d];
    float gp = a[1024+d]   + h[1024+d]   + bi[1024+d]   + bh[1024+d];
    float op = a[1536+d]   + h[1536+d]   + bi[1536+d]   + bh[1536+d];
    float i_g = sigf(ip);
    float f_g = sigf(fp);
    float g_g = tanhf(gp);
    float o_g = sigf(op);
    float c   = lstm_c[idx];
    float craw = f_g * c + i_g * g_g;
    float hn   = o_g * tanhf(craw);
    float dec  = decays[s];
    h_new[idx] = hn;
    c_new[idx] = dec * c + (1.0f - dec) * craw;
}

// sums kv/q split-K partials + biases
__global__ void r8_kernel(const float* __restrict__ kvp,
                          const float* __restrict__ qp,
                          const float* __restrict__ attn_in_b,
                          float* __restrict__ kv,
                          float* __restrict__ q)
{
    const int NKV = SS*BB*2*DD;   // 786432
    int idx = blockIdx.x * blockDim.x + threadIdx.x;
    if (idx < NKV) {
        int col = idx & 1023;
        kv[idx] = kvp[idx] + kvp[NKV + idx] + attn_in_b[512 + col];
    } else {
        int i2 = idx - NKV;
        if (i2 < BB*DD) {
            int col = i2 & 511;
            q[i2] = qp[i2] + qp[BB*DD + i2] + attn_in_b[col];
        }
    }
}

__global__ void attn_kernel(const float* __restrict__ q,
                            const float* __restrict__ kv,
                            float* __restrict__ ctx)
{
    int b    = blockIdx.x;
    int warp = threadIdx.x >> 5;
    int lane = threadIdx.x & 31;

    const float* qp = q + (long)b * DD + warp * 64;
    float q0 = qp[lane], q1 = qp[lane + 32];

    float sc[SS];
    #pragma unroll
    for (int s = 0; s < SS; s++) {
        const float* kp = kv + (long)(s*BB + b) * 1024 + warp * 64;
        float d = q0 * kp[lane] + q1 * kp[lane + 32];
        #pragma unroll
        for (int o = 16; o > 0; o >>= 1) d += __shfl_xor_sync(0xffffffff, d, o);
        sc[s] = d * 0.125f;
    }
    float m = fmaxf(sc[0], fmaxf(sc[1], sc[2]));
    float e[SS], sum = 0.0f;
    #pragma unroll
    for (int s = 0; s < SS; s++) { e[s] = expf(sc[s] - m); sum += e[s]; }
    float inv = 1.0f / sum;

    float c0 = 0.0f, c1 = 0.0f;
    #pragma unroll
    for (int s = 0; s < SS; s++) {
        const float* vp = kv + (long)(s*BB + b) * 1024 + 512 + warp * 64;
        float w = e[s] * inv;
        c0 += w * vp[lane];
        c1 += w * vp[lane + 32];
    }
    ctx[(long)b * DD + warp*64 + lane]      = c0;
    ctx[(long)b * DD + warp*64 + lane + 32] = c1;
}

// sum 10 proj partial planes + pvec -> layernorm -> out
__global__ void proj_ln_kernel(const float* __restrict__ part,
                               const float* __restrict__ pvec,
                               const float* __restrict__ g,
                               const float* __restrict__ be,
                               float* __restrict__ out)
{
    __shared__ float red[256];
    int row = blockIdx.x, t = threadIdx.x;
    long o0 = (long)row*DD + t, o1 = o0 + 256;
    const long PL = (long)BB*DD;
    float x0 = pvec[t], x1 = pvec[t+256];
    #pragma unroll
    for (int p = 0; p < 10; p++) { x0 += part[p*PL + o0]; x1 += part[p*PL + o1]; }

    red[t] = x0 + x1; __syncthreads();
    for (int o = 128; o > 0; o >>= 1) { if (t < o) red[t] += red[t+o]; __syncthreads(); }
    float mean = red[0] * (1.0f/DD);
    __syncthreads();

    float d0 = x0 - mean, d1 = x1 - mean;
    red[t] = d0*d0 + d1*d1; __syncthreads();
    for (int o = 128; o > 0; o >>= 1) { if (t < o) red[t] += red[t+o]; __syncthreads(); }
    float inv = rsqrtf(red[0] * (1.0f/DD) + 1e-5f);

    out[o0] = d0 * inv * g[t]     + be[t];
    out[o1] = d1 * inv * g[t+256] + be[t+256];
}

// ---------------------------------------------------------------------------
static inline GTask mk_task(const float* X, int ldX, const float* W, int ldW,
                            float* C, int ldC, int K, int kofs,
                            int mtiles, int ntiles)
{
    GTask t = {};
    t.X = X; t.ldX = ldX; t.W = W; t.ldW = ldW; t.C = C; t.ldC = ldC;
    t.K = K; t.kofs = kofs; t.nsplit = NOSPLIT;
    t.mtiles = mtiles; t.blocks = mtiles*ntiles;
    return t;
}

extern "C" void kernel_launch(void* const* d_in, const int* in_sizes, int n_in,
                              void* d_out, int out_size)
{
    (void)in_sizes; (void)n_in; (void)out_size;

    const float* x        = (const float*)d_in[0];
    const float* h_prev   = (const float*)d_in[1];
    const float* lstm_h   = (const float*)d_in[2];
    const float* lstm_c   = (const float*)d_in[3];
    const float* A        = (const float*)d_in[4];
    const float* Bm       = (const float*)d_in[5];
    const float* dn_w1    = (const float*)d_in[6];
    const float* dn_b1    = (const float*)d_in[7];
    const float* dn_g     = (const float*)d_in[8];
    const float* dn_beta  = (const float*)d_in[9];
    const float* dn_w2    = (const float*)d_in[10];
    const float* dn_b2    = (const float*)d_in[11];
    const float* lstm_wih = (const float*)d_in[12];
    const float* lstm_whh = (const float*)d_in[13];
    const float* lstm_bih = (const float*)d_in[14];
    const float* lstm_bhh = (const float*)d_in[15];
    const float* decays   = (const float*)d_in[16];
    const float* attn_in_w  = (const float*)d_in[17];
    const float* attn_in_b  = (const float*)d_in[18];
    const float* attn_out_w = (const float*)d_in[19];
    const float* attn_out_b = (const float*)d_in[20];
    const float* proj_w   = (const float*)d_in[21];
    const float* proj_b   = (const float*)d_in[22];
    const float* proj_g   = (const float*)d_in[23];
    const float* proj_beta= (const float*)d_in[24];

    float* out = (float*)d_out;
    float* out_y    = out;
    float* out_hssm = out + BB*DD;
    float* out_hnew = out + 2*BB*DD;
    float* out_cnew = out + 2*BB*DD + SS*BB*DD;

    float *p_h1, *p_delta, *p_bx, *p_T, *p_U, *p_AT, *p_A2T, *p_AoT, *p_M,
          *p_Wpow, *p_gA, *p_gB, *p_kvp, *p_qp, *p_q, *p_kv, *p_ctx,
          *p_part, *p_pvec;
    cudaGetSymbolAddress((void**)&p_h1,    g_h1);
    cudaGetSymbolAddress((void**)&p_delta, g_delta);
    cudaGetSymbolAddress((void**)&p_bx,    g_bx);
    cudaGetSymbolAddress((void**)&p_T,     g_T);
    cudaGetSymbolAddress((void**)&p_U,     g_U);
    cudaGetSymbolAddress((void**)&p_AT,    g_AT);
    cudaGetSymbolAddress((void**)&p_A2T,   g_A2T);
    cudaGetSymbolAddress((void**)&p_AoT,   g_AoT);
    cudaGetSymbolAddress((void**)&p_M,     g_M);
    cudaGetSymbolAddress((void**)&p_Wpow,  g_Wpow);
    cudaGetSymbolAddress((void**)&p_gA,    g_gA);
    cudaGetSymbolAddress((void**)&p_gB,    g_gB);
    cudaGetSymbolAddress((void**)&p_kvp,   g_kvp);
    cudaGetSymbolAddress((void**)&p_qp,    g_qp);
    cudaGetSymbolAddress((void**)&p_q,     g_q);
    cudaGetSymbolAddress((void**)&p_kv,    g_kv);
    cudaGetSymbolAddress((void**)&p_ctx,   g_ctx);
    cudaGetSymbolAddress((void**)&p_part,  g_part);
    cudaGetSymbolAddress((void**)&p_pvec,  g_pvec);

    // ---- T0: AT = A^T (+Wpow0 = A), AoT = attn_out_w^T ----
    transpose2_kernel<<<dim3(16,16,2), dim3(32,8)>>>(A, p_AT, p_Wpow,
                                                     attn_out_w, p_AoT);

    // ---- G1 (240 blocks): h1|bx, 6 lstm partials, A^2 (+A2T), M ----
    {
        GTaskSet ts = {};
        GTask t0 = mk_task(x, DD, dn_w1, DD, p_h1, DD, DD, 0, 2, 8);
        t0.bias = dn_b1; t0.Wn2 = Bm; t0.Cn2 = p_bx; t0.ldCn2 = DD; t0.nsplit = DD;
        ts.t[0] = t0;
        for (int s = 0; s < SS; s++) {
            ts.t[1+s] = mk_task(x, DD, lstm_wih + (long)s*4*DD*DD, DD,
                                p_gA + (long)s*BB*4*DD, 4*DD, DD, 0, 2, 16);
            ts.t[4+s] = mk_task(lstm_h + (long)s*BB*DD, DD,
                                lstm_whh + (long)s*4*DD*DD, DD,
                                p_gB + (long)s*BB*4*DD, 4*DD, DD, 0, 2, 16);
        }
        GTask ta = mk_task(A, DD, p_AT, DD, p_Wpow + (long)DD*DD, DD, DD, 0, 4, 4);
        ta.Ct = p_A2T; ta.ldCt = DD;
        ts.t[7] = ta;
        ts.t[8] = mk_task(proj_w + 512, 5*DD, p_AoT, DD, p_M, DD, DD, 0, 4, 4);
        ts.ntasks = 9;
        gemm_mma<<<240, 256>>>(ts);
    }

    delta_kernel<<<BB, 256>>>(p_h1, dn_g, dn_beta, dn_w2, dn_b2, p_delta);
    pvec_kernel<<<DD, 256>>>(proj_w, attn_out_b, proj_b, p_pvec);
    lstm_point_kernel<<<(SS*BB*DD)/256, 256>>>(
        p_gA, p_gB, lstm_bih, lstm_bhh, lstm_c, decays, out_hnew, out_cnew);

    // ---- G2 (32 blocks): A^3 = A^2 @ A, A^4 = A^2 @ A^2 ----
    {
        GTaskSet ts = {};
        ts.t[0] = mk_task(p_Wpow + (long)DD*DD, DD, p_AT, DD,
                          p_Wpow + 2L*DD*DD, DD, DD, 0, 4, 4);
        ts.t[1] = mk_task(p_Wpow + (long)DD*DD, DD, p_A2T, DD,
                          p_Wpow + 3L*DD*DD, DD, DD, 0, 4, 4);
        ts.ntasks = 2;
        gemm_mma<<<32, 256>>>(ts);
    }

    // ---- Taylor chain: 5 iters x 4 terms, split-K-4 (128 blocks) ----
    for (int it = 0; it < 5; it++) {
        const float* Xin = (it == 0) ? h_prev : p_T;
        GTaskSet ts = {};
        for (int kz = 0; kz < 4; kz++)
            ts.t[kz] = mk_task(Xin, DD, p_Wpow, DD,
                               p_U + (long)kz*BB*4*DD, 4*DD, 128, kz*128, 2, 16);
        ts.ntasks = 4;
        gemm_mma<<<128, 256>>>(ts);
        chain_epilogue_kernel<<<(BB*DD)/256, 256>>>(
            p_U, p_delta, p_T, out_hssm, h_prev, 4*it, p_bx, it == 4);
    }

    // ---- G8 (112 blocks): kv split-K-2, q split-K-2 ----
    {
        GTaskSet ts = {};
        for (int kz = 0; kz < 2; kz++) {
            ts.t[kz] = mk_task(out_hnew, DD, attn_in_w + (long)DD*DD, DD,
                               p_kvp + (long)kz*SS*BB*2*DD, 2*DD, 256, kz*256, 6, 8);
            ts.t[2+kz] = mk_task(out_hssm, DD, attn_in_w, DD,
                                 p_qp + (long)kz*BB*DD, DD, 256, kz*256, 2, 4);
        }
        ts.ntasks = 4;
        gemm_mma<<<112, 256>>>(ts);
    }
    r8_kernel<<<(SS*BB*2*DD + BB*DD + 255)/256, 256>>>(
        p_kvp, p_qp, attn_in_b, p_kv, p_q);

    // ---- attention ----
    attn_kernel<<<BB, 256>>>(p_q, p_kv, p_ctx);

    // ---- Gproj (80 blocks): 5 pieces x split-K-2 -> 10 partial planes ----
    {
        GTaskSet ts = {};
        int p = 0;
        for (int kz = 0; kz < 2; kz++, p++)
            ts.t[p] = mk_task(out_hssm, DD, proj_w, 5*DD,
                              p_part + (long)p*BB*DD, DD, 256, kz*256, 2, 4);
        for (int kz = 0; kz < 2; kz++, p++)
            ts.t[p] = mk_task(p_ctx, DD, p_M, DD,
                              p_part + (long)p*BB*DD, DD, 256, kz*256, 2, 4);
        for (int i = 0; i < SS; i++)
            for (int kz = 0; kz < 2; kz++, p++)
                ts.t[p] = mk_task(out_hnew + (long)i*BB*DD, DD,
                                  proj_w + 1024 + i*512, 5*DD,
                                  p_part + (long)p*BB*DD, DD, 256, kz*256, 2, 4);
        ts.ntasks = 10;
        gemm_mma<<<80, 256>>>(ts);
    }

    // ---- reduce + LN -> out_y ----
    proj_ln_kernel<<<BB, 256>>>(p_part, p_pvec, proj_g, proj_beta, out_y);
}